// round 5
// baseline (speedup 1.0000x reference)
#include <cuda_runtime.h>
#include <math.h>

#define NN 46080
#define BBG 64
#define BLKG 720
#define EE 400000
#define CX 128
#define CE 32
#define SORTN 16384
#define OFF_X 0
#define OFF_EIO 5898240
#define OFF_ATTR 6698240
#define OFF_BATCH 19498240
#define OFF_XG 19544320

typedef unsigned long long u64;
typedef unsigned int u32;

__device__ int g_rs[NN + 1];
__device__ int g_rev[EE];
__device__ float g_ns[NN * CE];
__device__ float g_ea[EE * CE];
__device__ double g_bnstat[2 * CE];
__device__ float g_bna[CE], g_bnd[CE];
__device__ float g_snr;
__device__ float g_score[EE];
__device__ double g_gsum[BBG];
__device__ float g_gmean[BBG];
__device__ unsigned char g_sel[EE];
__device__ int g_xmask[NN];
__device__ int g_lab[NN];
__device__ int g_repcnt[BBG];
__device__ int g_rb[BBG + 1];
__device__ int g_comp[NN];
__device__ int g_bout[NN];
__device__ float g_h[NN * CX];
__device__ float g_t1[NN * CX];
__device__ float g_xc[NN * CX];
__device__ float g_pa[NN * CX];
__device__ float g_pb[NN * CX];
__device__ int g_has[NN];
__device__ float g_xg[BBG * CX];
__device__ u64 g_sorted[BBG * SORTN];
__device__ int g_urank[BBG * SORTN];
__device__ int g_ucnt[BBG];
__device__ int g_ub[BBG + 1];

// ---------------- init ----------------
__global__ void k_init(float* out) {
    int i = blockIdx.x * blockDim.x + threadIdx.x;
    if (i < EE * CE) out[OFF_ATTR + i] = 0.f;
    if (i < NN * CX) { g_pa[i] = 0.f; g_pb[i] = 0.f; }
    if (i < 2 * EE) out[OFF_EIO + i] = -1.f;
    if (i < NN) { g_xmask[i] = 0; g_has[i] = 0; g_bout[i] = 0; }
    if (i < BBG * CX) g_xg[i] = 0.f;
    if (i < 2 * CE) g_bnstat[i] = 0.0;
    if (i < BBG) g_gsum[i] = 0.0;
}

// ---------------- rowstart via binary search ----------------
__global__ void k_rowstart(const int* __restrict__ row) {
    int r = blockIdx.x * blockDim.x + threadIdx.x;
    if (r > NN) return;
    int lo = 0, hi = EE;
    while (lo < hi) { int m = (lo + hi) >> 1; if (row[m] < r) lo = m + 1; else hi = m; }
    g_rs[r] = lo;
}

// ---------------- reverse edge index ----------------
__global__ void k_rev(const int* __restrict__ row, const int* __restrict__ col) {
    int e = blockIdx.x * blockDim.x + threadIdx.x;
    if (e >= EE) return;
    int t = col[e], v = row[e];
    int lo = g_rs[t], hi = g_rs[t + 1];
    while (lo < hi) { int m = (lo + hi) >> 1; if (col[m] < v) lo = m + 1; else hi = m; }
    g_rev[e] = lo;
}

// ---------------- nodesum[n][c] = sum over in-edges of attr (via rev) ----------
__global__ void k_nodesum(const float* __restrict__ eattr) {
    int w = (blockIdx.x * blockDim.x + threadIdx.x) >> 5;
    int l = threadIdx.x & 31;
    if (w >= NN) return;
    float s = 0.f;
    for (int e = g_rs[w]; e < g_rs[w + 1]; e++) s += eattr[g_rev[e] * CE + l];
    g_ns[w * CE + l] = s;
}

// ---------------- ea = (ns[row]+attr) @ We + be, BN stats (double) -------------
__global__ void k_lin(const int* __restrict__ row, const float* __restrict__ eattr,
                      const float* __restrict__ We, const float* __restrict__ be) {
    __shared__ float Ws[CE * CE], bs[CE];
    __shared__ float wsum[8][CE], wsq[8][CE];
    int t = threadIdx.x;
    for (int i = t; i < CE * CE; i += 256) Ws[i] = We[i];
    if (t < CE) bs[t] = be[t];
    __syncthreads();
    int e = blockIdx.x * 256 + t;
    float in[CE], o[CE];
    if (e < EE) {
        int r = row[e];
        #pragma unroll
        for (int k = 0; k < CE; k += 4) {
            float4 a = *(const float4*)&g_ns[r * CE + k];
            float4 b = *(const float4*)&eattr[e * CE + k];
            in[k] = a.x + b.x; in[k+1] = a.y + b.y; in[k+2] = a.z + b.z; in[k+3] = a.w + b.w;
        }
    } else {
        #pragma unroll
        for (int k = 0; k < CE; k++) in[k] = 0.f;
    }
    #pragma unroll 4
    for (int j = 0; j < CE; j++) {
        float a = (e < EE) ? bs[j] : 0.f;
        #pragma unroll
        for (int k = 0; k < CE; k++) a += in[k] * Ws[k * CE + j];
        o[j] = a;
    }
    if (e < EE) {
        #pragma unroll
        for (int j = 0; j < CE; j += 4)
            *(float4*)&g_ea[e * CE + j] = make_float4(o[j], o[j+1], o[j+2], o[j+3]);
    }
    int wid = t >> 5, l = t & 31;
    for (int j = 0; j < CE; j++) {
        float v = o[j], v2 = v * v;
        for (int off = 16; off; off >>= 1) {
            v += __shfl_down_sync(~0u, v, off);
            v2 += __shfl_down_sync(~0u, v2, off);
        }
        if (l == 0) { wsum[wid][j] = v; wsq[wid][j] = v2; }
    }
    __syncthreads();
    if (t < CE) {
        float s = 0.f, q = 0.f;
        for (int w = 0; w < 8; w++) { s += wsum[w][t]; q += wsq[w][t]; }
        atomicAdd(&g_bnstat[t], (double)s);
        atomicAdd(&g_bnstat[CE + t], (double)q);
    }
}

__global__ void k_bnfin(const float* __restrict__ g, const float* __restrict__ b) {
    int j = threadIdx.x;
    if (j >= CE) return;
    double mu = g_bnstat[j] / (double)EE;
    double var = g_bnstat[CE + j] / (double)EE - mu * mu;
    float a = g[j] / (float)sqrt(var + 1e-5);
    g_bna[j] = a; g_bnd[j] = b[j] - (float)mu * a;
}

__global__ void k_bnapply() {
    int i = blockIdx.x * blockDim.x + threadIdx.x;
    if (i >= EE * CE / 4) return;
    int c0 = (i & 7) * 4;
    float4 v = *(float4*)&g_ea[i * 4];
    v.x = fmaxf(v.x * g_bna[c0] + g_bnd[c0], 0.f);
    v.y = fmaxf(v.y * g_bna[c0+1] + g_bnd[c0+1], 0.f);
    v.z = fmaxf(v.z * g_bna[c0+2] + g_bnd[c0+2], 0.f);
    v.w = fmaxf(v.w * g_bna[c0+3] + g_bnd[c0+3], 0.f);
    *(float4*)&g_ea[i * 4] = v;
}

__global__ void k_snorm(const float* __restrict__ S) {
    int l = threadIdx.x;
    float v = S[l] * S[l];
    for (int o = 16; o; o >>= 1) v += __shfl_down_sync(~0u, v, o);
    if (l == 0) g_snr = sqrtf(v);
}

// ---------------- score + per-graph sums (double) ----------------
__global__ void k_score(const int* __restrict__ row, const float* __restrict__ S) {
    __shared__ double sloc[2];
    __shared__ float Ss[CE];
    int t = threadIdx.x;
    if (t < 2) sloc[t] = 0.0;
    if (t < CE) Ss[t] = S[t];
    __syncthreads();
    int e = blockIdx.x * 256 + t;
    int g0 = row[min(blockIdx.x * 256, EE - 1)] / BLKG;
    if (e < EE) {
        int re = g_rev[e];
        float z = 0.f;
        #pragma unroll
        for (int k = 0; k < CE; k++) z += (g_ea[e * CE + k] + g_ea[re * CE + k]) * Ss[k];
        float s = 1.f / (1.f + expf(-z / g_snr));
        g_score[e] = s;
        int gg = row[e] / BLKG;
        atomicAdd(&sloc[gg == g0 ? 0 : 1], (double)s);
    }
    __syncthreads();
    if (t == 0) {
        atomicAdd(&g_gsum[g0], sloc[0]);
        int g1 = row[min(blockIdx.x * 256 + 255, EE - 1)] / BLKG;
        if (g1 != g0 && sloc[1] != 0.0) atomicAdd(&g_gsum[g1], sloc[1]);
    }
}

__global__ void k_gmean() {
    int g = threadIdx.x;
    if (g >= BBG) return;
    int c = g_rs[(g + 1) * BLKG] - g_rs[g * BLKG];
    g_gmean[g] = c ? (float)(g_gsum[g] / (double)c) : 0.f;
}

__global__ void k_sel(const int* __restrict__ row) {
    int e = blockIdx.x * blockDim.x + threadIdx.x;
    if (e >= EE) return;
    float s = g_score[e];
    int g = row[e] / BLKG;
    unsigned char sl = (s <= 0.5f) && (s < g_gmean[g]);
    g_sel[e] = sl;
    if (sl) g_xmask[row[e]] = 1;
    #pragma unroll
    for (int k = 0; k < CE; k += 4) {
        float4 v = *(float4*)&g_ea[e * CE + k];
        v.x *= s; v.y *= s; v.z *= s; v.w *= s;
        *(float4*)&g_ea[e * CE + k] = v;
    }
}

// ---------------- per-graph connected components ----------------
__global__ void k_cc(const int* __restrict__ row, const int* __restrict__ col) {
    __shared__ int lab[BLKG];
    __shared__ int chg, rc;
    int g = blockIdx.x, t = threadIdx.x;
    int base = g * BLKG;
    int e0 = g_rs[base], e1 = g_rs[base + BLKG];
    for (int i = t; i < BLKG; i += blockDim.x) lab[i] = i;
    if (t == 0) { chg = 1; rc = 0; }
    __syncthreads();
    for (int it = 0; it < 256 && chg; it++) {
        __syncthreads();
        if (t == 0) chg = 0;
        __syncthreads();
        for (int e = e0 + t; e < e1; e += blockDim.x) {
            if (!g_sel[e]) continue;
            int r = row[e] - base, c = col[e] - base;
            int lr = lab[r], lc = lab[c];
            if (lr < lc) { if (atomicMin(&lab[c], lr) > lr) chg = 1; }
            else if (lc < lr) { if (atomicMin(&lab[r], lc) > lc) chg = 1; }
        }
        __syncthreads();
        for (int i = t; i < BLKG; i += blockDim.x) {
            int l = lab[i], ll = lab[l];
            if (ll < l) { lab[i] = ll; chg = 1; }
        }
        __syncthreads();
    }
    for (int i = t; i < BLKG; i += blockDim.x) {
        g_lab[base + i] = lab[i];
        if (lab[i] == i) atomicAdd(&rc, 1);
    }
    __syncthreads();
    if (t == 0) g_repcnt[g] = rc;
}

__global__ void k_scan64() {
    if (threadIdx.x == 0) {
        int a = 0;
        for (int g = 0; g < BBG; g++) { g_rb[g] = a; a += g_repcnt[g]; }
        g_rb[BBG] = a;
    }
}

__global__ void k_comp() {
    __shared__ int s[1024];
    int g = blockIdx.x, t = threadIdx.x;
    int base = g * BLKG;
    s[t] = (t < BLKG && g_lab[base + t] == t) ? 1 : 0;
    __syncthreads();
    for (int off = 1; off < 1024; off <<= 1) {
        int v = (t >= off) ? s[t - off] : 0;
        __syncthreads(); s[t] += v; __syncthreads();
    }
    if (t < BLKG) {
        int c = g_rb[g] + s[g_lab[base + t]] - 1;
        g_comp[base + t] = c;
        g_bout[c] = g;
    }
}

// ---------------- EGIN message + aggregate -> g_h ----------------
__global__ void k_msg2(const float* __restrict__ x, const float* __restrict__ Wedge,
                       const float* __restrict__ eps, const int* __restrict__ col) {
    __shared__ float Ws[CE * CX];
    int t = threadIdx.x;
    for (int i = t; i < CE * CX; i += 256) Ws[i] = Wedge[i];
    __syncthreads();
    int n = (blockIdx.x * 256 + t) >> 5;
    int l = t & 31;
    if (n >= NN) return;
    float4 agg = make_float4(0.f, 0.f, 0.f, 0.f);
    for (int e = g_rs[n]; e < g_rs[n + 1]; e++) {
        if (!g_sel[e]) continue;
        float4 m = make_float4(0.f, 0.f, 0.f, 0.f);
        #pragma unroll 8
        for (int k = 0; k < CE; k++) {
            float ek = __ldg(&g_ea[e * CE + k]);
            float4 w = *(const float4*)&Ws[k * CX + l * 4];
            m.x += ek * w.x; m.y += ek * w.y; m.z += ek * w.z; m.w += ek * w.w;
        }
        const float4 xc = *(const float4*)&x[(size_t)col[e] * CX + l * 4];
        agg.x += fmaxf(m.x + xc.x, 0.f); agg.y += fmaxf(m.y + xc.y, 0.f);
        agg.z += fmaxf(m.z + xc.z, 0.f); agg.w += fmaxf(m.w + xc.w, 0.f);
    }
    float ep = 1.f + eps[0];
    const float4 xn = *(const float4*)&x[(size_t)n * CX + l * 4];
    float4 h = make_float4(ep * xn.x + agg.x, ep * xn.y + agg.y,
                           ep * xn.z + agg.z, ep * xn.w + agg.w);
    *(float4*)&g_h[(size_t)n * CX + l * 4] = h;
}

// ---------------- GEMM [NN,128]@[128,128] + bias (+relu) ----------------------
// which=0: g_t1 = relu(g_h @ W + b);  which=1: g_xc = g_t1 @ W + b
// (buffers bound in DEVICE code — passing __device__ symbols from host is UB)
__global__ void k_gemm(const float* __restrict__ W, const float* __restrict__ bias,
                       int which) {
    const float* A = which ? g_t1 : g_h;
    float* C = which ? g_xc : g_t1;
    int relu = (which == 0);
    __shared__ float As[64 * 32];
    __shared__ float Bs[32 * CX];
    int t = threadIdx.x;
    int m0 = blockIdx.x * 64;
    int tx = t & 31, ty = t >> 5;
    float4 acc[8];
    #pragma unroll
    for (int i = 0; i < 8; i++) acc[i] = make_float4(0.f, 0.f, 0.f, 0.f);
    for (int k0 = 0; k0 < CX; k0 += 32) {
        for (int i = t; i < 64 * 32; i += 256) As[i] = A[(size_t)(m0 + (i >> 5)) * CX + k0 + (i & 31)];
        for (int i = t; i < 32 * CX; i += 256) Bs[i] = W[(size_t)(k0 + (i >> 7)) * CX + (i & 127)];
        __syncthreads();
        #pragma unroll 8
        for (int kk = 0; kk < 32; kk++) {
            float4 b = *(float4*)&Bs[kk * CX + tx * 4];
            #pragma unroll
            for (int i = 0; i < 8; i++) {
                float a = As[(ty * 8 + i) * 32 + kk];
                acc[i].x += a * b.x; acc[i].y += a * b.y; acc[i].z += a * b.z; acc[i].w += a * b.w;
            }
        }
        __syncthreads();
    }
    float4 bb = *(const float4*)&bias[tx * 4];
    #pragma unroll
    for (int i = 0; i < 8; i++) {
        float4 o = make_float4(acc[i].x + bb.x, acc[i].y + bb.y, acc[i].z + bb.z, acc[i].w + bb.w);
        if (relu) { o.x = fmaxf(o.x, 0.f); o.y = fmaxf(o.y, 0.f); o.z = fmaxf(o.z, 0.f); o.w = fmaxf(o.w, 0.f); }
        *(float4*)&C[(size_t)(m0 + ty * 8 + i) * CX + tx * 4] = o;
    }
}

// ---------------- pooling ----------------
__global__ void k_pool(const float* __restrict__ x) {
    int i = blockIdx.x * blockDim.x + threadIdx.x;
    if (i >= NN * 32) return;
    int n = i >> 5, q = (i & 31) * 4;
    int c = g_comp[n];
    if (g_xmask[n]) {
        float4 v = *(const float4*)&g_xc[(size_t)n * CX + q];
        atomicAdd(&g_pa[(size_t)c * CX + q], v.x); atomicAdd(&g_pa[(size_t)c * CX + q + 1], v.y);
        atomicAdd(&g_pa[(size_t)c * CX + q + 2], v.z); atomicAdd(&g_pa[(size_t)c * CX + q + 3], v.w);
    } else {
        float4 v = *(const float4*)&x[(size_t)n * CX + q];
        atomicAdd(&g_pb[(size_t)c * CX + q], v.x); atomicAdd(&g_pb[(size_t)c * CX + q + 1], v.y);
        atomicAdd(&g_pb[(size_t)c * CX + q + 2], v.z); atomicAdd(&g_pb[(size_t)c * CX + q + 3], v.w);
        if ((i & 31) == 0) g_has[c] = 1;
    }
}

__global__ void k_xout(float* out) {
    int i = blockIdx.x * blockDim.x + threadIdx.x;
    if (i >= NN * 32) return;
    int cl = i >> 5, q = (i & 31) * 4;
    int h = g_has[cl];
    float4 a = *(float4*)&g_pa[(size_t)cl * CX + q];
    float4 b = *(float4*)&g_pb[(size_t)cl * CX + q];
    float4 o = h ? b : a;
    *(float4*)&out[OFF_X + (size_t)cl * CX + q] = o;
    if ((i & 31) == 0) out[OFF_BATCH + cl] = (float)g_bout[cl];
    if (cl < g_rb[BBG]) {
        int bg = g_bout[cl];
        atomicAdd(&g_xg[bg * CX + q], o.x); atomicAdd(&g_xg[bg * CX + q + 1], o.y);
        atomicAdd(&g_xg[bg * CX + q + 2], o.z); atomicAdd(&g_xg[bg * CX + q + 3], o.w);
    }
}

__global__ void k_bnxg(const float* __restrict__ g, const float* __restrict__ b, float* out) {
    int c = threadIdx.x;
    if (c >= CX) return;
    double s = 0.0, q = 0.0;
    for (int i = 0; i < BBG; i++) { double v = g_xg[i * CX + c]; s += v; q += v * v; }
    double mu = s / BBG, var = q / BBG - mu * mu;
    float a = g[c] / (float)sqrt(var + 1e-5);
    float d = b[c] - (float)mu * a;
    for (int i = 0; i < BBG; i++) out[OFF_XG + i * CX + c] = g_xg[i * CX + c] * a + d;
}

// ---------------- per-graph sort of coalesce keys ----------------
__global__ void k_sort(const int* __restrict__ row, const int* __restrict__ col) {
    extern __shared__ u64 sd[];
    __shared__ int scnt;
    __shared__ int part[1024];
    int g = blockIdx.x, t = threadIdx.x;
    int e0 = g_rs[g * BLKG], e1 = g_rs[(g + 1) * BLKG];
    if (t == 0) scnt = 0;
    for (int i = t; i < SORTN; i += 1024) sd[i] = ~0ull;
    __syncthreads();
    for (int e = e0 + t; e < e1; e += 1024) {
        if (g_sel[e]) continue;
        u32 key = (u32)g_comp[row[e]] * (u32)NN + (u32)g_comp[col[e]];
        int p = atomicAdd(&scnt, 1);
        if (p < SORTN) sd[p] = ((u64)key << 32) | (u32)e;
    }
    __syncthreads();
    if (scnt > 0) {
        for (u32 k = 2; k <= SORTN; k <<= 1)
            for (u32 j = k >> 1; j; j >>= 1) {
                for (u32 i = t; i < SORTN; i += 1024) {
                    u32 ixj = i ^ j;
                    if (ixj > i) {
                        u64 a = sd[i], bb = sd[ixj];
                        bool up = ((i & k) == 0);
                        if ((a > bb) == up) { sd[i] = bb; sd[ixj] = a; }
                    }
                }
                __syncthreads();
            }
    }
    for (int i = t; i < SORTN; i += 1024) g_sorted[g * SORTN + i] = sd[i];
    __syncthreads();
    int i0 = t * 16, lp[16], run = 0;
    #pragma unroll
    for (int j = 0; j < 16; j++) {
        int i = i0 + j;
        u32 key = (u32)(sd[i] >> 32);
        int f = (key != 0xffffffffu) && (i == 0 || (u32)(sd[i - 1] >> 32) != key);
        run += f; lp[j] = run;
    }
    part[t] = run;
    __syncthreads();
    for (int off = 1; off < 1024; off <<= 1) {
        int v = (t >= off) ? part[t - off] : 0;
        __syncthreads(); part[t] += v; __syncthreads();
    }
    int base = (t ? part[t - 1] : 0);
    #pragma unroll
    for (int j = 0; j < 16; j++) g_urank[g * SORTN + i0 + j] = base + lp[j];
    if (t == 1023) g_ucnt[g] = part[1023];
}

__global__ void k_uscan() {
    if (threadIdx.x == 0) {
        int a = 0;
        for (int g = 0; g < BBG; g++) { g_ub[g] = a; a += g_ucnt[g]; }
        g_ub[BBG] = a;
    }
}

__global__ void k_emit(float* out) {
    int g = blockIdx.x, t = threadIdx.x;
    const u64* sd = &g_sorted[g * SORTN];
    for (int i = t; i < SORTN; i += 1024) {
        u32 key = (u32)(sd[i] >> 32);
        if (key == 0xffffffffu) continue;
        if (i > 0 && (u32)(sd[i - 1] >> 32) == key) continue;
        int seg = g_ub[g] + g_urank[g * SORTN + i] - 1;
        float acc[CE];
        #pragma unroll
        for (int c = 0; c < CE; c++) acc[c] = 0.f;
        int j = i;
        while (j < SORTN && (u32)(sd[j] >> 32) == key) {
            int e = (int)(u32)sd[j];
            #pragma unroll
            for (int c = 0; c < CE; c++) acc[c] += g_ea[e * CE + c];
            j++;
        }
        for (int c = 0; c < CE; c += 4)
            *(float4*)&out[OFF_ATTR + (size_t)seg * CE + c] =
                make_float4(acc[c], acc[c+1], acc[c+2], acc[c+3]);
        out[OFF_EIO + seg] = (float)(key / (u32)NN);
        out[OFF_EIO + EE + seg] = (float)(key % (u32)NN);
    }
}

extern "C" void kernel_launch(void* const* d_in, const int* in_sizes, int n_in,
                              void* d_out, int out_size) {
    const int* ei = (const int*)d_in[1];
    const float* x = (const float*)d_in[0];
    const float* eattr = (const float*)d_in[2];
    const float* S = (const float*)d_in[4];
    const float* We = (const float*)d_in[5];
    const float* be = (const float*)d_in[6];
    const float* bn_e_g = (const float*)d_in[7];
    const float* bn_e_b = (const float*)d_in[8];
    const float* Wedge = (const float*)d_in[9];
    const float* eps = (const float*)d_in[10];
    const float* W1 = (const float*)d_in[11];
    const float* b1 = (const float*)d_in[12];
    const float* W2 = (const float*)d_in[13];
    const float* b2 = (const float*)d_in[14];
    const float* bn_g = (const float*)d_in[15];
    const float* bn_b = (const float*)d_in[16];
    float* out = (float*)d_out;
    const int* row = ei;
    const int* col = ei + EE;

    cudaFuncSetAttribute(k_sort, cudaFuncAttributeMaxDynamicSharedMemorySize, SORTN * 8);

    k_init<<<(EE * CE + 255) / 256, 256>>>(out);
    k_rowstart<<<(NN + 256) / 256, 256>>>(row);
    k_rev<<<(EE + 255) / 256, 256>>>(row, col);
    k_nodesum<<<(NN * 32 + 255) / 256, 256>>>(eattr);
    k_lin<<<(EE + 255) / 256, 256>>>(row, eattr, We, be);
    k_bnfin<<<1, 32>>>(bn_e_g, bn_e_b);
    k_bnapply<<<(EE * CE / 4 + 255) / 256, 256>>>();
    k_snorm<<<1, 32>>>(S);
    k_score<<<(EE + 255) / 256, 256>>>(row, S);
    k_gmean<<<1, 64>>>();
    k_sel<<<(EE + 255) / 256, 256>>>(row);
    k_cc<<<BBG, 768>>>(row, col);
    k_scan64<<<1, 32>>>();
    k_comp<<<BBG, 1024>>>();
    k_msg2<<<(NN * 32 + 255) / 256, 256>>>(x, Wedge, eps, col);
    k_gemm<<<NN / 64, 256>>>(W1, b1, 0);
    k_gemm<<<NN / 64, 256>>>(W2, b2, 1);
    k_pool<<<(NN * 32 + 255) / 256, 256>>>(x);
    k_xout<<<(NN * 32 + 255) / 256, 256>>>(out);
    k_bnxg<<<1, 128>>>(bn_g, bn_b, out);
    k_sort<<<BBG, 1024, SORTN * 8>>>(row, col);
    k_uscan<<<1, 32>>>();
    k_emit<<<BBG, 1024>>>(out);
}

// round 6
// speedup vs baseline: 4.3102x; 4.3102x over previous
#include <cuda_runtime.h>
#include <math.h>

#define NN 46080
#define BBG 64
#define BLKG 720
#define EE 400000
#define CX 128
#define CE 32
#define SORTN 16384
#define OFF_X 0
#define OFF_EIO 5898240
#define OFF_ATTR 6698240
#define OFF_BATCH 19498240
#define OFF_XG 19544320

typedef unsigned long long u64;
typedef unsigned int u32;

__device__ int g_rs[NN + 1];
__device__ int g_rev[EE];
__device__ float g_ns[NN * CE];
__device__ float g_ea[EE * CE];
__device__ double g_bnstat[2 * CE];
__device__ float g_bna[CE], g_bnd[CE];
__device__ float g_snr;
__device__ float g_score[EE];
__device__ double g_gsum[BBG];
__device__ float g_gmean[BBG];
__device__ unsigned char g_sel[EE];
__device__ int g_xmask[NN];
__device__ int g_lab[NN];
__device__ int g_repcnt[BBG];
__device__ int g_rb[BBG + 1];
__device__ int g_comp[NN];
__device__ int g_bout[NN];
__device__ float g_h[NN * CX];
__device__ float g_t1[NN * CX];
__device__ float g_xc[NN * CX];
__device__ float g_pa[NN * CX];
__device__ float g_pb[NN * CX];
__device__ int g_has[NN];
__device__ float g_xg[BBG * CX];
__device__ u64 g_sorted[BBG * SORTN];
__device__ int g_urank[BBG * SORTN];
__device__ int g_ucnt[BBG];
__device__ int g_ub[BBG + 1];

// ---------------- init ----------------
__global__ void k_init(float* out) {
    int i = blockIdx.x * blockDim.x + threadIdx.x;
    if (i < EE * CE) out[OFF_ATTR + i] = 0.f;
    if (i < NN * CX) { g_pa[i] = 0.f; g_pb[i] = 0.f; }
    if (i < 2 * EE) out[OFF_EIO + i] = -1.f;
    if (i < NN) { g_xmask[i] = 0; g_has[i] = 0; g_bout[i] = 0; }
    if (i < BBG * CX) g_xg[i] = 0.f;
    if (i < 2 * CE) g_bnstat[i] = 0.0;
    if (i < BBG) g_gsum[i] = 0.0;
}

// ---------------- rowstart via binary search ----------------
__global__ void k_rowstart(const int* __restrict__ row) {
    int r = blockIdx.x * blockDim.x + threadIdx.x;
    if (r > NN) return;
    int lo = 0, hi = EE;
    while (lo < hi) { int m = (lo + hi) >> 1; if (row[m] < r) lo = m + 1; else hi = m; }
    g_rs[r] = lo;
}

// ---------------- reverse edge index ----------------
__global__ void k_rev(const int* __restrict__ row, const int* __restrict__ col) {
    int e = blockIdx.x * blockDim.x + threadIdx.x;
    if (e >= EE) return;
    int t = col[e], v = row[e];
    int lo = g_rs[t], hi = g_rs[t + 1];
    while (lo < hi) { int m = (lo + hi) >> 1; if (col[m] < v) lo = m + 1; else hi = m; }
    g_rev[e] = lo;
}

// ---------------- nodesum[n][c] = sum over in-edges of attr (via rev) ----------
__global__ void k_nodesum(const float* __restrict__ eattr) {
    int w = (blockIdx.x * blockDim.x + threadIdx.x) >> 5;
    int l = threadIdx.x & 31;
    if (w >= NN) return;
    float s = 0.f;
    for (int e = g_rs[w]; e < g_rs[w + 1]; e++) s += eattr[g_rev[e] * CE + l];
    g_ns[w * CE + l] = s;
}

// ---------------- raw linear: ea = (ns[row]+attr) @ We + be, BN stats (double) --
__global__ void k_lin(const int* __restrict__ row, const float* __restrict__ eattr,
                      const float* __restrict__ We, const float* __restrict__ be) {
    __shared__ float Ws[CE * CE], bs[CE];
    __shared__ float wsum[8][CE], wsq[8][CE];
    int t = threadIdx.x;
    for (int i = t; i < CE * CE; i += 256) Ws[i] = We[i];
    if (t < CE) bs[t] = be[t];
    __syncthreads();
    int e = blockIdx.x * 256 + t;
    float in[CE], o[CE];
    if (e < EE) {
        int r = row[e];
        #pragma unroll
        for (int k = 0; k < CE; k += 4) {
            float4 a = *(const float4*)&g_ns[r * CE + k];
            float4 b = *(const float4*)&eattr[e * CE + k];
            in[k] = a.x + b.x; in[k+1] = a.y + b.y; in[k+2] = a.z + b.z; in[k+3] = a.w + b.w;
        }
    } else {
        #pragma unroll
        for (int k = 0; k < CE; k++) in[k] = 0.f;
    }
    #pragma unroll 4
    for (int j = 0; j < CE; j++) {
        float a = (e < EE) ? bs[j] : 0.f;
        #pragma unroll
        for (int k = 0; k < CE; k++) a += in[k] * Ws[k * CE + j];
        o[j] = a;
    }
    if (e < EE) {
        #pragma unroll
        for (int j = 0; j < CE; j += 4)
            *(float4*)&g_ea[e * CE + j] = make_float4(o[j], o[j+1], o[j+2], o[j+3]);
    }
    int wid = t >> 5, l = t & 31;
    for (int j = 0; j < CE; j++) {
        float v = o[j], v2 = v * v;
        for (int off = 16; off; off >>= 1) {
            v += __shfl_down_sync(~0u, v, off);
            v2 += __shfl_down_sync(~0u, v2, off);
        }
        if (l == 0) { wsum[wid][j] = v; wsq[wid][j] = v2; }
    }
    __syncthreads();
    if (t < CE) {
        float s = 0.f, q = 0.f;
        for (int w = 0; w < 8; w++) { s += wsum[w][t]; q += wsq[w][t]; }
        atomicAdd(&g_bnstat[t], (double)s);
        atomicAdd(&g_bnstat[CE + t], (double)q);
    }
}

__global__ void k_bnfin(const float* __restrict__ g, const float* __restrict__ b) {
    int j = threadIdx.x;
    if (j >= CE) return;
    double mu = g_bnstat[j] / (double)EE;
    double var = g_bnstat[CE + j] / (double)EE - mu * mu;
    float a = g[j] / (float)sqrt(var + 1e-5);
    g_bna[j] = a; g_bnd[j] = b[j] - (float)mu * a;
}

__global__ void k_snorm(const float* __restrict__ S) {
    int l = threadIdx.x;
    float v = S[l] * S[l];
    for (int o = 16; o; o >>= 1) v += __shfl_down_sync(~0u, v, o);
    if (l == 0) g_snr = sqrtf(v);
}

// ---------------- score (BN+ReLU fused on the fly) + per-graph sums (double) ---
__global__ void k_score(const int* __restrict__ row, const float* __restrict__ S) {
    __shared__ double sloc[2];
    __shared__ float Ss[CE], Ba[CE], Bd[CE];
    int t = threadIdx.x;
    if (t < 2) sloc[t] = 0.0;
    if (t < CE) { Ss[t] = S[t]; Ba[t] = g_bna[t]; Bd[t] = g_bnd[t]; }
    __syncthreads();
    int e = blockIdx.x * 256 + t;
    int g0 = row[min(blockIdx.x * 256, EE - 1)] / BLKG;
    if (e < EE) {
        int re = g_rev[e];
        float z = 0.f;
        #pragma unroll
        for (int k = 0; k < CE; k++) {
            float u = fmaxf(g_ea[e * CE + k] * Ba[k] + Bd[k], 0.f)
                    + fmaxf(g_ea[re * CE + k] * Ba[k] + Bd[k], 0.f);
            z += u * Ss[k];
        }
        float s = 1.f / (1.f + expf(-z / g_snr));
        g_score[e] = s;
        int gg = row[e] / BLKG;
        atomicAdd(&sloc[gg == g0 ? 0 : 1], (double)s);
    }
    __syncthreads();
    if (t == 0) {
        atomicAdd(&g_gsum[g0], sloc[0]);
        int g1 = row[min(blockIdx.x * 256 + 255, EE - 1)] / BLKG;
        if (g1 != g0 && sloc[1] != 0.0) atomicAdd(&g_gsum[g1], sloc[1]);
    }
}

__global__ void k_gmean() {
    int g = threadIdx.x;
    if (g >= BBG) return;
    int c = g_rs[(g + 1) * BLKG] - g_rs[g * BLKG];
    g_gmean[g] = c ? (float)(g_gsum[g] / (double)c) : 0.f;
}

// ---------------- selection + finalize ea = relu(bn(lin)) * score --------------
__global__ void k_sel(const int* __restrict__ row) {
    int e = blockIdx.x * blockDim.x + threadIdx.x;
    if (e >= EE) return;
    float s = g_score[e];
    int g = row[e] / BLKG;
    unsigned char sl = (s <= 0.5f) && (s < g_gmean[g]);
    g_sel[e] = sl;
    if (sl) g_xmask[row[e]] = 1;
    #pragma unroll
    for (int k = 0; k < CE; k += 4) {
        float4 v = *(float4*)&g_ea[e * CE + k];
        v.x = fmaxf(v.x * g_bna[k]   + g_bnd[k],   0.f) * s;
        v.y = fmaxf(v.y * g_bna[k+1] + g_bnd[k+1], 0.f) * s;
        v.z = fmaxf(v.z * g_bna[k+2] + g_bnd[k+2], 0.f) * s;
        v.w = fmaxf(v.w * g_bna[k+3] + g_bnd[k+3], 0.f) * s;
        *(float4*)&g_ea[e * CE + k] = v;
    }
}

// ---------------- per-graph connected components ----------------
__global__ void k_cc(const int* __restrict__ row, const int* __restrict__ col) {
    __shared__ int lab[BLKG];
    __shared__ int chg, rc;
    int g = blockIdx.x, t = threadIdx.x;
    int base = g * BLKG;
    int e0 = g_rs[base], e1 = g_rs[base + BLKG];
    for (int i = t; i < BLKG; i += blockDim.x) lab[i] = i;
    if (t == 0) { chg = 1; rc = 0; }
    __syncthreads();
    for (int it = 0; it < 256 && chg; it++) {
        __syncthreads();
        if (t == 0) chg = 0;
        __syncthreads();
        for (int e = e0 + t; e < e1; e += blockDim.x) {
            if (!g_sel[e]) continue;
            int r = row[e] - base, c = col[e] - base;
            int lr = lab[r], lc = lab[c];
            if (lr < lc) { if (atomicMin(&lab[c], lr) > lr) chg = 1; }
            else if (lc < lr) { if (atomicMin(&lab[r], lc) > lc) chg = 1; }
        }
        __syncthreads();
        for (int i = t; i < BLKG; i += blockDim.x) {
            int l = lab[i], ll = lab[l];
            if (ll < l) { lab[i] = ll; chg = 1; }
        }
        __syncthreads();
    }
    for (int i = t; i < BLKG; i += blockDim.x) {
        g_lab[base + i] = lab[i];
        if (lab[i] == i) atomicAdd(&rc, 1);
    }
    __syncthreads();
    if (t == 0) g_repcnt[g] = rc;
}

__global__ void k_scan64() {
    if (threadIdx.x == 0) {
        int a = 0;
        for (int g = 0; g < BBG; g++) { g_rb[g] = a; a += g_repcnt[g]; }
        g_rb[BBG] = a;
    }
}

__global__ void k_comp() {
    __shared__ int s[1024];
    int g = blockIdx.x, t = threadIdx.x;
    int base = g * BLKG;
    s[t] = (t < BLKG && g_lab[base + t] == t) ? 1 : 0;
    __syncthreads();
    for (int off = 1; off < 1024; off <<= 1) {
        int v = (t >= off) ? s[t - off] : 0;
        __syncthreads(); s[t] += v; __syncthreads();
    }
    if (t < BLKG) {
        int c = g_rb[g] + s[g_lab[base + t]] - 1;
        g_comp[base + t] = c;
        g_bout[c] = g;
    }
}

// ---------------- EGIN message + aggregate -> g_h ----------------
__global__ void k_msg2(const float* __restrict__ x, const float* __restrict__ Wedge,
                       const float* __restrict__ eps, const int* __restrict__ col) {
    __shared__ float Ws[CE * CX];
    int t = threadIdx.x;
    for (int i = t; i < CE * CX; i += 256) Ws[i] = Wedge[i];
    __syncthreads();
    int n = (blockIdx.x * 256 + t) >> 5;
    int l = t & 31;
    if (n >= NN) return;
    float4 agg = make_float4(0.f, 0.f, 0.f, 0.f);
    for (int e = g_rs[n]; e < g_rs[n + 1]; e++) {
        if (!g_sel[e]) continue;
        float4 m = make_float4(0.f, 0.f, 0.f, 0.f);
        #pragma unroll 8
        for (int k = 0; k < CE; k++) {
            float ek = __ldg(&g_ea[e * CE + k]);
            float4 w = *(const float4*)&Ws[k * CX + l * 4];
            m.x += ek * w.x; m.y += ek * w.y; m.z += ek * w.z; m.w += ek * w.w;
        }
        const float4 xc = *(const float4*)&x[(size_t)col[e] * CX + l * 4];
        agg.x += fmaxf(m.x + xc.x, 0.f); agg.y += fmaxf(m.y + xc.y, 0.f);
        agg.z += fmaxf(m.z + xc.z, 0.f); agg.w += fmaxf(m.w + xc.w, 0.f);
    }
    float ep = 1.f + eps[0];
    const float4 xn = *(const float4*)&x[(size_t)n * CX + l * 4];
    float4 h = make_float4(ep * xn.x + agg.x, ep * xn.y + agg.y,
                           ep * xn.z + agg.z, ep * xn.w + agg.w);
    *(float4*)&g_h[(size_t)n * CX + l * 4] = h;
}

// ---------------- GEMM [NN,128]@[128,128] + bias (+relu) ----------------------
__global__ void k_gemm(const float* __restrict__ W, const float* __restrict__ bias,
                       int which) {
    const float* A = which ? g_t1 : g_h;
    float* C = which ? g_xc : g_t1;
    int relu = (which == 0);
    __shared__ float As[64 * 32];
    __shared__ float Bs[32 * CX];
    int t = threadIdx.x;
    int m0 = blockIdx.x * 64;
    int tx = t & 31, ty = t >> 5;
    float4 acc[8];
    #pragma unroll
    for (int i = 0; i < 8; i++) acc[i] = make_float4(0.f, 0.f, 0.f, 0.f);
    for (int k0 = 0; k0 < CX; k0 += 32) {
        for (int i = t; i < 64 * 32; i += 256) As[i] = A[(size_t)(m0 + (i >> 5)) * CX + k0 + (i & 31)];
        for (int i = t; i < 32 * CX; i += 256) Bs[i] = W[(size_t)(k0 + (i >> 7)) * CX + (i & 127)];
        __syncthreads();
        #pragma unroll 8
        for (int kk = 0; kk < 32; kk++) {
            float4 b = *(float4*)&Bs[kk * CX + tx * 4];
            #pragma unroll
            for (int i = 0; i < 8; i++) {
                float a = As[(ty * 8 + i) * 32 + kk];
                acc[i].x += a * b.x; acc[i].y += a * b.y; acc[i].z += a * b.z; acc[i].w += a * b.w;
            }
        }
        __syncthreads();
    }
    float4 bb = *(const float4*)&bias[tx * 4];
    #pragma unroll
    for (int i = 0; i < 8; i++) {
        float4 o = make_float4(acc[i].x + bb.x, acc[i].y + bb.y, acc[i].z + bb.z, acc[i].w + bb.w);
        if (relu) { o.x = fmaxf(o.x, 0.f); o.y = fmaxf(o.y, 0.f); o.z = fmaxf(o.z, 0.f); o.w = fmaxf(o.w, 0.f); }
        *(float4*)&C[(size_t)(m0 + ty * 8 + i) * CX + tx * 4] = o;
    }
}

// ---------------- pooling ----------------
__global__ void k_pool(const float* __restrict__ x) {
    int i = blockIdx.x * blockDim.x + threadIdx.x;
    if (i >= NN * 32) return;
    int n = i >> 5, q = (i & 31) * 4;
    int c = g_comp[n];
    if (g_xmask[n]) {
        float4 v = *(const float4*)&g_xc[(size_t)n * CX + q];
        atomicAdd(&g_pa[(size_t)c * CX + q], v.x); atomicAdd(&g_pa[(size_t)c * CX + q + 1], v.y);
        atomicAdd(&g_pa[(size_t)c * CX + q + 2], v.z); atomicAdd(&g_pa[(size_t)c * CX + q + 3], v.w);
    } else {
        float4 v = *(const float4*)&x[(size_t)n * CX + q];
        atomicAdd(&g_pb[(size_t)c * CX + q], v.x); atomicAdd(&g_pb[(size_t)c * CX + q + 1], v.y);
        atomicAdd(&g_pb[(size_t)c * CX + q + 2], v.z); atomicAdd(&g_pb[(size_t)c * CX + q + 3], v.w);
        if ((i & 31) == 0) g_has[c] = 1;
    }
}

__global__ void k_xout(float* out) {
    int i = blockIdx.x * blockDim.x + threadIdx.x;
    if (i >= NN * 32) return;
    int cl = i >> 5, q = (i & 31) * 4;
    int h = g_has[cl];
    float4 a = *(float4*)&g_pa[(size_t)cl * CX + q];
    float4 b = *(float4*)&g_pb[(size_t)cl * CX + q];
    float4 o = h ? b : a;
    *(float4*)&out[OFF_X + (size_t)cl * CX + q] = o;
    if ((i & 31) == 0) out[OFF_BATCH + cl] = (float)g_bout[cl];
    if (cl < g_rb[BBG]) {
        int bg = g_bout[cl];
        atomicAdd(&g_xg[bg * CX + q], o.x); atomicAdd(&g_xg[bg * CX + q + 1], o.y);
        atomicAdd(&g_xg[bg * CX + q + 2], o.z); atomicAdd(&g_xg[bg * CX + q + 3], o.w);
    }
}

__global__ void k_bnxg(const float* __restrict__ g, const float* __restrict__ b, float* out) {
    int c = threadIdx.x;
    if (c >= CX) return;
    double s = 0.0, q = 0.0;
    for (int i = 0; i < BBG; i++) { double v = g_xg[i * CX + c]; s += v; q += v * v; }
    double mu = s / BBG, var = q / BBG - mu * mu;
    float a = g[c] / (float)sqrt(var + 1e-5);
    float d = b[c] - (float)mu * a;
    for (int i = 0; i < BBG; i++) out[OFF_XG + i * CX + c] = g_xg[i * CX + c] * a + d;
}

// ---------------- per-graph sort of coalesce keys (pow2-trimmed) ---------------
__global__ void k_sort(const int* __restrict__ row, const int* __restrict__ col) {
    extern __shared__ u64 sd[];
    __shared__ int scnt, Ppow;
    __shared__ int part[1024];
    int g = blockIdx.x, t = threadIdx.x;
    int e0 = g_rs[g * BLKG], e1 = g_rs[(g + 1) * BLKG];
    if (t == 0) scnt = 0;
    for (int i = t; i < SORTN; i += 1024) sd[i] = ~0ull;
    __syncthreads();
    for (int e = e0 + t; e < e1; e += 1024) {
        if (g_sel[e]) continue;
        u32 key = (u32)g_comp[row[e]] * (u32)NN + (u32)g_comp[col[e]];
        int p = atomicAdd(&scnt, 1);
        if (p < SORTN) sd[p] = ((u64)key << 32) | (u32)e;
    }
    __syncthreads();
    if (t == 0) { int P = 2; while (P < scnt) P <<= 1; Ppow = P; }
    __syncthreads();
    int P = Ppow;
    if (scnt > 0) {
        for (u32 k = 2; k <= (u32)P; k <<= 1)
            for (u32 j = k >> 1; j; j >>= 1) {
                for (u32 i = t; i < (u32)P; i += 1024) {
                    u32 ixj = i ^ j;
                    if (ixj > i) {
                        u64 a = sd[i], bb = sd[ixj];
                        bool up = ((i & k) == 0);
                        if ((a > bb) == up) { sd[i] = bb; sd[ixj] = a; }
                    }
                }
                __syncthreads();
            }
    }
    for (int i = t; i < SORTN; i += 1024) g_sorted[g * SORTN + i] = sd[i];
    __syncthreads();
    int i0 = t * 16, lp[16], run = 0;
    #pragma unroll
    for (int j = 0; j < 16; j++) {
        int i = i0 + j;
        u32 key = (u32)(sd[i] >> 32);
        int f = (key != 0xffffffffu) && (i == 0 || (u32)(sd[i - 1] >> 32) != key);
        run += f; lp[j] = run;
    }
    part[t] = run;
    __syncthreads();
    for (int off = 1; off < 1024; off <<= 1) {
        int v = (t >= off) ? part[t - off] : 0;
        __syncthreads(); part[t] += v; __syncthreads();
    }
    int base = (t ? part[t - 1] : 0);
    #pragma unroll
    for (int j = 0; j < 16; j++) g_urank[g * SORTN + i0 + j] = base + lp[j];
    if (t == 1023) g_ucnt[g] = part[1023];
}

__global__ void k_uscan() {
    if (threadIdx.x == 0) {
        int a = 0;
        for (int g = 0; g < BBG; g++) { g_ub[g] = a; a += g_ucnt[g]; }
        g_ub[BBG] = a;
    }
}

// ---------------- emit: fully parallel via atomics (no serial run walk) --------
__global__ void k_emit(float* out) {
    int g = blockIdx.x, t = threadIdx.x;
    const u64* sd = &g_sorted[g * SORTN];
    const int* ur = &g_urank[g * SORTN];
    int ubg = g_ub[g];
    for (int i = t; i < SORTN; i += 1024) {
        u64 v = sd[i];
        u32 key = (u32)(v >> 32);
        if (key == 0xffffffffu) continue;
        int seg = ubg + ur[i] - 1;
        int e = (int)(u32)v;
        float* dst = &out[OFF_ATTR + (size_t)seg * CE];
        const float* src = &g_ea[e * CE];
        #pragma unroll
        for (int c = 0; c < CE; c += 4) {
            float4 a = *(const float4*)&src[c];
            atomicAdd(&dst[c], a.x); atomicAdd(&dst[c + 1], a.y);
            atomicAdd(&dst[c + 2], a.z); atomicAdd(&dst[c + 3], a.w);
        }
        if (i == 0 || (u32)(sd[i - 1] >> 32) != key) {
            out[OFF_EIO + seg] = (float)(key / (u32)NN);
            out[OFF_EIO + EE + seg] = (float)(key % (u32)NN);
        }
    }
}

extern "C" void kernel_launch(void* const* d_in, const int* in_sizes, int n_in,
                              void* d_out, int out_size) {
    const int* ei = (const int*)d_in[1];
    const float* x = (const float*)d_in[0];
    const float* eattr = (const float*)d_in[2];
    const float* S = (const float*)d_in[4];
    const float* We = (const float*)d_in[5];
    const float* be = (const float*)d_in[6];
    const float* bn_e_g = (const float*)d_in[7];
    const float* bn_e_b = (const float*)d_in[8];
    const float* Wedge = (const float*)d_in[9];
    const float* eps = (const float*)d_in[10];
    const float* W1 = (const float*)d_in[11];
    const float* b1 = (const float*)d_in[12];
    const float* W2 = (const float*)d_in[13];
    const float* b2 = (const float*)d_in[14];
    const float* bn_g = (const float*)d_in[15];
    const float* bn_b = (const float*)d_in[16];
    float* out = (float*)d_out;
    const int* row = ei;
    const int* col = ei + EE;

    cudaFuncSetAttribute(k_sort, cudaFuncAttributeMaxDynamicSharedMemorySize, SORTN * 8);

    k_init<<<(EE * CE + 255) / 256, 256>>>(out);
    k_rowstart<<<(NN + 256) / 256, 256>>>(row);
    k_rev<<<(EE + 255) / 256, 256>>>(row, col);
    k_nodesum<<<(NN * 32 + 255) / 256, 256>>>(eattr);
    k_lin<<<(EE + 255) / 256, 256>>>(row, eattr, We, be);
    k_bnfin<<<1, 32>>>(bn_e_g, bn_e_b);
    k_snorm<<<1, 32>>>(S);
    k_score<<<(EE + 255) / 256, 256>>>(row, S);
    k_gmean<<<1, 64>>>();
    k_sel<<<(EE + 255) / 256, 256>>>(row);
    k_cc<<<BBG, 768>>>(row, col);
    k_scan64<<<1, 32>>>();
    k_comp<<<BBG, 1024>>>();
    k_msg2<<<(NN * 32 + 255) / 256, 256>>>(x, Wedge, eps, col);
    k_gemm<<<NN / 64, 256>>>(W1, b1, 0);
    k_gemm<<<NN / 64, 256>>>(W2, b2, 1);
    k_pool<<<(NN * 32 + 255) / 256, 256>>>(x);
    k_xout<<<(NN * 32 + 255) / 256, 256>>>(out);
    k_bnxg<<<1, 128>>>(bn_g, bn_b, out);
    k_sort<<<BBG, 1024, SORTN * 8>>>(row, col);
    k_uscan<<<1, 32>>>();
    k_emit<<<BBG, 1024>>>(out);
}

// round 7
// speedup vs baseline: 6.1355x; 1.4235x over previous
#include <cuda_runtime.h>
#include <math.h>

#define NN 46080
#define BBG 64
#define BLKG 720
#define EE 400000
#define CX 128
#define CE 32
#define SORTN 16384
#define HSH 16384
#define OFF_X 0
#define OFF_EIO 5898240
#define OFF_ATTR 6698240
#define OFF_BATCH 19498240
#define OFF_XG 19544320

typedef unsigned long long u64;
typedef unsigned int u32;

__device__ int g_rs[NN + 1];
__device__ int g_rev[EE];
__device__ float g_ns[NN * CE];
__device__ float g_ea[EE * CE];
__device__ double g_bnstat[2 * CE];
__device__ float g_bna[CE], g_bnd[CE];
__device__ float g_snr;
__device__ float g_score[EE];
__device__ double g_gsum[BBG];
__device__ float g_gmean[BBG];
__device__ unsigned char g_sel[EE];
__device__ int g_xmask[NN];
__device__ int g_lab[NN];
__device__ int g_repcnt[BBG];
__device__ int g_rb[BBG + 1];
__device__ int g_comp[NN];
__device__ int g_bout[NN];
__device__ float g_h[NN * CX];
__device__ float g_t1[NN * CX];
__device__ float g_xc[NN * CX];
__device__ float g_pa[NN * CX];
__device__ float g_pb[NN * CX];
__device__ int g_has[NN];
__device__ float g_xg[BBG * CX];
__device__ u32 g_ukeys[BBG * SORTN];
__device__ int g_erank[EE];
__device__ int g_ucnt[BBG];
__device__ int g_ub[BBG + 1];

// ---------------- init ----------------
__global__ void k_init(float* out) {
    int i = blockIdx.x * blockDim.x + threadIdx.x;
    if (i < EE * CE) out[OFF_ATTR + i] = 0.f;
    if (i < NN * CX) { g_pa[i] = 0.f; g_pb[i] = 0.f; }
    if (i < 2 * EE) out[OFF_EIO + i] = -1.f;
    if (i < NN) { g_xmask[i] = 0; g_has[i] = 0; g_bout[i] = 0; }
    if (i < BBG * CX) g_xg[i] = 0.f;
    if (i < 2 * CE) g_bnstat[i] = 0.0;
    if (i < BBG) g_gsum[i] = 0.0;
}

// ---------------- rowstart via binary search ----------------
__global__ void k_rowstart(const int* __restrict__ row) {
    int r = blockIdx.x * blockDim.x + threadIdx.x;
    if (r > NN) return;
    int lo = 0, hi = EE;
    while (lo < hi) { int m = (lo + hi) >> 1; if (row[m] < r) lo = m + 1; else hi = m; }
    g_rs[r] = lo;
}

// ---------------- reverse edge index ----------------
__global__ void k_rev(const int* __restrict__ row, const int* __restrict__ col) {
    int e = blockIdx.x * blockDim.x + threadIdx.x;
    if (e >= EE) return;
    int t = col[e], v = row[e];
    int lo = g_rs[t], hi = g_rs[t + 1];
    while (lo < hi) { int m = (lo + hi) >> 1; if (col[m] < v) lo = m + 1; else hi = m; }
    g_rev[e] = lo;
}

// ---------------- nodesum[n][c] = sum over in-edges of attr (via rev) ----------
__global__ void k_nodesum(const float* __restrict__ eattr) {
    int w = (blockIdx.x * blockDim.x + threadIdx.x) >> 5;
    int l = threadIdx.x & 31;
    if (w >= NN) return;
    float s = 0.f;
    for (int e = g_rs[w]; e < g_rs[w + 1]; e++) s += eattr[g_rev[e] * CE + l];
    g_ns[w * CE + l] = s;
}

// ---------------- raw linear: ea = (ns[row]+attr) @ We + be --------------------
__global__ void k_lin(const int* __restrict__ row, const float* __restrict__ eattr,
                      const float* __restrict__ We, const float* __restrict__ be) {
    __shared__ float Ws[CE * CE], bs[CE];
    int t = threadIdx.x;
    for (int i = t; i < CE * CE; i += 256) Ws[i] = We[i];
    if (t < CE) bs[t] = be[t];
    __syncthreads();
    int e = blockIdx.x * 256 + t;
    if (e >= EE) return;
    float in[CE], o[CE];
    int r = row[e];
    #pragma unroll
    for (int k = 0; k < CE; k += 4) {
        float4 a = *(const float4*)&g_ns[r * CE + k];
        float4 b = *(const float4*)&eattr[e * CE + k];
        in[k] = a.x + b.x; in[k+1] = a.y + b.y; in[k+2] = a.z + b.z; in[k+3] = a.w + b.w;
    }
    #pragma unroll 4
    for (int j = 0; j < CE; j++) {
        float a = bs[j];
        #pragma unroll
        for (int k = 0; k < CE; k++) a += in[k] * Ws[k * CE + j];
        o[j] = a;
    }
    #pragma unroll
    for (int j = 0; j < CE; j += 4)
        *(float4*)&g_ea[e * CE + j] = make_float4(o[j], o[j+1], o[j+2], o[j+3]);
}

// ---------------- BN statistics: coalesced warp-per-chunk pass over g_ea -------
__global__ void k_bnstats() {
    int w = (blockIdx.x * blockDim.x + threadIdx.x) >> 5;
    int l = threadIdx.x & 31;
    int nw = (gridDim.x * blockDim.x) >> 5;
    double s = 0.0, q = 0.0;
    for (int e = w; e < EE; e += nw) {
        float v = g_ea[e * CE + l];
        s += v; q += (double)v * v;
    }
    atomicAdd(&g_bnstat[l], s);
    atomicAdd(&g_bnstat[CE + l], q);
}

// ---------------- BN finalize + S norm (merged) ----------------
__global__ void k_bnfin(const float* __restrict__ g, const float* __restrict__ b,
                        const float* __restrict__ S) {
    int j = threadIdx.x;
    float v = S[j] * S[j];
    for (int o = 16; o; o >>= 1) v += __shfl_down_sync(~0u, v, o);
    if (j == 0) g_snr = sqrtf(v);
    double mu = g_bnstat[j] / (double)EE;
    double var = g_bnstat[CE + j] / (double)EE - mu * mu;
    float a = g[j] / (float)sqrt(var + 1e-5);
    g_bna[j] = a; g_bnd[j] = b[j] - (float)mu * a;
}

// ---------------- score (BN+ReLU fused, float4) + per-graph sums (double) ------
__global__ void k_score(const int* __restrict__ row, const float* __restrict__ S) {
    __shared__ double sloc[2];
    __shared__ float Ss[CE], Ba[CE], Bd[CE];
    int t = threadIdx.x;
    if (t < 2) sloc[t] = 0.0;
    if (t < CE) { Ss[t] = S[t]; Ba[t] = g_bna[t]; Bd[t] = g_bnd[t]; }
    __syncthreads();
    int e = blockIdx.x * 256 + t;
    int g0 = row[min(blockIdx.x * 256, EE - 1)] / BLKG;
    if (e < EE) {
        int re = g_rev[e];
        float z = 0.f;
        #pragma unroll
        for (int k = 0; k < CE; k += 4) {
            float4 a = *(const float4*)&g_ea[e * CE + k];
            float4 b = *(const float4*)&g_ea[re * CE + k];
            z += (fmaxf(a.x * Ba[k]   + Bd[k],   0.f) + fmaxf(b.x * Ba[k]   + Bd[k],   0.f)) * Ss[k];
            z += (fmaxf(a.y * Ba[k+1] + Bd[k+1], 0.f) + fmaxf(b.y * Ba[k+1] + Bd[k+1], 0.f)) * Ss[k+1];
            z += (fmaxf(a.z * Ba[k+2] + Bd[k+2], 0.f) + fmaxf(b.z * Ba[k+2] + Bd[k+2], 0.f)) * Ss[k+2];
            z += (fmaxf(a.w * Ba[k+3] + Bd[k+3], 0.f) + fmaxf(b.w * Ba[k+3] + Bd[k+3], 0.f)) * Ss[k+3];
        }
        float s = 1.f / (1.f + expf(-z / g_snr));
        g_score[e] = s;
        int gg = row[e] / BLKG;
        atomicAdd(&sloc[gg == g0 ? 0 : 1], (double)s);
    }
    __syncthreads();
    if (t == 0) {
        atomicAdd(&g_gsum[g0], sloc[0]);
        int g1 = row[min(blockIdx.x * 256 + 255, EE - 1)] / BLKG;
        if (g1 != g0 && sloc[1] != 0.0) atomicAdd(&g_gsum[g1], sloc[1]);
    }
}

__global__ void k_gmean() {
    int g = threadIdx.x;
    if (g >= BBG) return;
    int c = g_rs[(g + 1) * BLKG] - g_rs[g * BLKG];
    g_gmean[g] = c ? (float)(g_gsum[g] / (double)c) : 0.f;
}

// ---------------- selection + finalize ea = relu(bn(lin)) * score --------------
__global__ void k_sel(const int* __restrict__ row) {
    __shared__ float Ba[CE], Bd[CE];
    int t = threadIdx.x;
    if (t < CE) { Ba[t] = g_bna[t]; Bd[t] = g_bnd[t]; }
    __syncthreads();
    int e = blockIdx.x * 256 + t;
    if (e >= EE) return;
    float s = g_score[e];
    int g = row[e] / BLKG;
    unsigned char sl = (s <= 0.5f) && (s < g_gmean[g]);
    g_sel[e] = sl;
    if (sl) g_xmask[row[e]] = 1;
    #pragma unroll
    for (int k = 0; k < CE; k += 4) {
        float4 v = *(float4*)&g_ea[e * CE + k];
        v.x = fmaxf(v.x * Ba[k]   + Bd[k],   0.f) * s;
        v.y = fmaxf(v.y * Ba[k+1] + Bd[k+1], 0.f) * s;
        v.z = fmaxf(v.z * Ba[k+2] + Bd[k+2], 0.f) * s;
        v.w = fmaxf(v.w * Ba[k+3] + Bd[k+3], 0.f) * s;
        *(float4*)&g_ea[e * CE + k] = v;
    }
}

// ---------------- per-graph connected components (smem edge cache) -------------
__global__ void k_cc(const int* __restrict__ row, const int* __restrict__ col) {
    extern __shared__ u32 eb[];         // packed selected edges r<<10 | c
    __shared__ int lab[BLKG];
    __shared__ int chg, rc, ecnt;
    int g = blockIdx.x, t = threadIdx.x;
    int base = g * BLKG;
    int e0 = g_rs[base], e1 = g_rs[base + BLKG];
    for (int i = t; i < BLKG; i += blockDim.x) lab[i] = i;
    if (t == 0) { chg = 1; rc = 0; ecnt = 0; }
    __syncthreads();
    for (int e = e0 + t; e < e1; e += blockDim.x) {
        if (!g_sel[e]) continue;
        int p = atomicAdd(&ecnt, 1);
        eb[p] = ((u32)(row[e] - base) << 10) | (u32)(col[e] - base);
    }
    __syncthreads();
    int ne = ecnt;
    for (int it = 0; it < 256 && chg; it++) {
        __syncthreads();
        if (t == 0) chg = 0;
        __syncthreads();
        for (int i = t; i < ne; i += blockDim.x) {
            u32 p = eb[i];
            int r = p >> 10, c = p & 1023;
            int lr = lab[r], lc = lab[c];
            if (lr < lc) { if (atomicMin(&lab[c], lr) > lr) chg = 1; }
            else if (lc < lr) { if (atomicMin(&lab[r], lc) > lc) chg = 1; }
        }
        __syncthreads();
        for (int i = t; i < BLKG; i += blockDim.x) {
            int l = lab[i], ll = lab[l];
            if (ll < l) { lab[i] = ll; chg = 1; }
        }
        __syncthreads();
    }
    for (int i = t; i < BLKG; i += blockDim.x) {
        g_lab[base + i] = lab[i];
        if (lab[i] == i) atomicAdd(&rc, 1);
    }
    __syncthreads();
    if (t == 0) g_repcnt[g] = rc;
}

__global__ void k_scan64() {
    if (threadIdx.x == 0) {
        int a = 0;
        for (int g = 0; g < BBG; g++) { g_rb[g] = a; a += g_repcnt[g]; }
        g_rb[BBG] = a;
    }
}

__global__ void k_comp() {
    __shared__ int s[1024];
    int g = blockIdx.x, t = threadIdx.x;
    int base = g * BLKG;
    s[t] = (t < BLKG && g_lab[base + t] == t) ? 1 : 0;
    __syncthreads();
    for (int off = 1; off < 1024; off <<= 1) {
        int v = (t >= off) ? s[t - off] : 0;
        __syncthreads(); s[t] += v; __syncthreads();
    }
    if (t < BLKG) {
        int c = g_rb[g] + s[g_lab[base + t]] - 1;
        g_comp[base + t] = c;
        g_bout[c] = g;
    }
}

// ---------------- unique coalesce keys via smem hash + tiny sort ----------------
__global__ void k_unique(const int* __restrict__ row, const int* __restrict__ col) {
    extern __shared__ u32 sh[];
    u32* hkey  = sh;             // [HSH]
    u32* hrank = sh + HSH;       // [HSH]
    u32* ulist = sh + 2 * HSH;   // [HSH]
    __shared__ int part[1024];
    int g = blockIdx.x, t = threadIdx.x;
    int e0 = g_rs[g * BLKG], e1 = g_rs[(g + 1) * BLKG];
    for (int i = t; i < HSH; i += 1024) hkey[i] = 0xFFFFFFFFu;
    __syncthreads();
    // hash-insert all unselected-edge keys; remember slot per edge
    for (int e = e0 + t; e < e1; e += 1024) {
        if (g_sel[e]) continue;
        u32 key = (u32)g_comp[row[e]] * (u32)NN + (u32)g_comp[col[e]];
        u32 h = (key * 2654435761u) & (HSH - 1);
        while (true) {
            u32 old = atomicCAS(&hkey[h], 0xFFFFFFFFu, key);
            if (old == 0xFFFFFFFFu || old == key) break;
            h = (h + 1) & (HSH - 1);
        }
        g_erank[e] = (int)h;
    }
    __syncthreads();
    // compact occupied slots into ulist
    int i0 = t * 16, run = 0;
    for (int j = 0; j < 16; j++) run += (hkey[i0 + j] != 0xFFFFFFFFu);
    part[t] = run;
    __syncthreads();
    for (int off = 1; off < 1024; off <<= 1) {
        int v = (t >= off) ? part[t - off] : 0;
        __syncthreads(); part[t] += v; __syncthreads();
    }
    int base = t ? part[t - 1] : 0;
    int w = 0;
    for (int j = 0; j < 16; j++) {
        u32 k2 = hkey[i0 + j];
        if (k2 != 0xFFFFFFFFu) ulist[base + w++] = k2;
    }
    int U = part[1023];
    if (t == 0) g_ucnt[g] = U;
    __syncthreads();
    // pad + bitonic sort (tiny: U is usually small)
    int P = 2; while (P < U) P <<= 1;
    for (int i = U + t; i < P; i += 1024) ulist[i] = 0xFFFFFFFFu;
    __syncthreads();
    for (u32 k = 2; k <= (u32)P; k <<= 1)
        for (u32 j = k >> 1; j; j >>= 1) {
            for (u32 i = t; i < (u32)P; i += 1024) {
                u32 ixj = i ^ j;
                if (ixj > i) {
                    u32 a = ulist[i], b = ulist[ixj];
                    bool up = ((i & k) == 0);
                    if ((a > b) == up) { ulist[i] = b; ulist[ixj] = a; }
                }
            }
            __syncthreads();
        }
    // write sorted rank into hash; persist sorted keys
    for (int p = t; p < U; p += 1024) {
        u32 key = ulist[p];
        u32 h = (key * 2654435761u) & (HSH - 1);
        while (hkey[h] != key) h = (h + 1) & (HSH - 1);
        hrank[h] = (u32)p;
        g_ukeys[g * SORTN + p] = key;
    }
    __syncthreads();
    // per-edge slot -> rank
    for (int e = e0 + t; e < e1; e += 1024) {
        if (g_sel[e]) continue;
        g_erank[e] = (int)hrank[g_erank[e]];
    }
}

__global__ void k_uscan() {
    if (threadIdx.x == 0) {
        int a = 0;
        for (int g = 0; g < BBG; g++) { g_ub[g] = a; a += g_ucnt[g]; }
        g_ub[BBG] = a;
    }
}

// ---------------- EGIN message + aggregate -> g_h ----------------
__global__ void k_msg2(const float* __restrict__ x, const float* __restrict__ Wedge,
                       const float* __restrict__ eps, const int* __restrict__ col) {
    __shared__ float Ws[CE * CX];
    int t = threadIdx.x;
    for (int i = t; i < CE * CX; i += 256) Ws[i] = Wedge[i];
    __syncthreads();
    int n = (blockIdx.x * 256 + t) >> 5;
    int l = t & 31;
    if (n >= NN) return;
    float4 agg = make_float4(0.f, 0.f, 0.f, 0.f);
    for (int e = g_rs[n]; e < g_rs[n + 1]; e++) {
        if (!g_sel[e]) continue;
        float4 m = make_float4(0.f, 0.f, 0.f, 0.f);
        #pragma unroll 8
        for (int k = 0; k < CE; k++) {
            float ek = __ldg(&g_ea[e * CE + k]);
            float4 w = *(const float4*)&Ws[k * CX + l * 4];
            m.x += ek * w.x; m.y += ek * w.y; m.z += ek * w.z; m.w += ek * w.w;
        }
        const float4 xc = *(const float4*)&x[(size_t)col[e] * CX + l * 4];
        agg.x += fmaxf(m.x + xc.x, 0.f); agg.y += fmaxf(m.y + xc.y, 0.f);
        agg.z += fmaxf(m.z + xc.z, 0.f); agg.w += fmaxf(m.w + xc.w, 0.f);
    }
    float ep = 1.f + eps[0];
    const float4 xn = *(const float4*)&x[(size_t)n * CX + l * 4];
    float4 h = make_float4(ep * xn.x + agg.x, ep * xn.y + agg.y,
                           ep * xn.z + agg.z, ep * xn.w + agg.w);
    *(float4*)&g_h[(size_t)n * CX + l * 4] = h;
}

// ---------------- GEMM [NN,128]@[128,128] + bias (+relu) ----------------------
__global__ void k_gemm(const float* __restrict__ W, const float* __restrict__ bias,
                       int which) {
    const float* A = which ? g_t1 : g_h;
    float* C = which ? g_xc : g_t1;
    int relu = (which == 0);
    __shared__ float As[64 * 32];
    __shared__ float Bs[32 * CX];
    int t = threadIdx.x;
    int m0 = blockIdx.x * 64;
    int tx = t & 31, ty = t >> 5;
    float4 acc[8];
    #pragma unroll
    for (int i = 0; i < 8; i++) acc[i] = make_float4(0.f, 0.f, 0.f, 0.f);
    for (int k0 = 0; k0 < CX; k0 += 32) {
        for (int i = t; i < 64 * 32; i += 256) As[i] = A[(size_t)(m0 + (i >> 5)) * CX + k0 + (i & 31)];
        for (int i = t; i < 32 * CX; i += 256) Bs[i] = W[(size_t)(k0 + (i >> 7)) * CX + (i & 127)];
        __syncthreads();
        #pragma unroll 8
        for (int kk = 0; kk < 32; kk++) {
            float4 b = *(float4*)&Bs[kk * CX + tx * 4];
            #pragma unroll
            for (int i = 0; i < 8; i++) {
                float a = As[(ty * 8 + i) * 32 + kk];
                acc[i].x += a * b.x; acc[i].y += a * b.y; acc[i].z += a * b.z; acc[i].w += a * b.w;
            }
        }
        __syncthreads();
    }
    float4 bb = *(const float4*)&bias[tx * 4];
    #pragma unroll
    for (int i = 0; i < 8; i++) {
        float4 o = make_float4(acc[i].x + bb.x, acc[i].y + bb.y, acc[i].z + bb.z, acc[i].w + bb.w);
        if (relu) { o.x = fmaxf(o.x, 0.f); o.y = fmaxf(o.y, 0.f); o.z = fmaxf(o.z, 0.f); o.w = fmaxf(o.w, 0.f); }
        *(float4*)&C[(size_t)(m0 + ty * 8 + i) * CX + tx * 4] = o;
    }
}

// ---------------- pooling ----------------
__global__ void k_pool(const float* __restrict__ x) {
    int i = blockIdx.x * blockDim.x + threadIdx.x;
    if (i >= NN * 32) return;
    int n = i >> 5, q = (i & 31) * 4;
    int c = g_comp[n];
    if (g_xmask[n]) {
        float4 v = *(const float4*)&g_xc[(size_t)n * CX + q];
        atomicAdd(&g_pa[(size_t)c * CX + q], v.x); atomicAdd(&g_pa[(size_t)c * CX + q + 1], v.y);
        atomicAdd(&g_pa[(size_t)c * CX + q + 2], v.z); atomicAdd(&g_pa[(size_t)c * CX + q + 3], v.w);
    } else {
        float4 v = *(const float4*)&x[(size_t)n * CX + q];
        atomicAdd(&g_pb[(size_t)c * CX + q], v.x); atomicAdd(&g_pb[(size_t)c * CX + q + 1], v.y);
        atomicAdd(&g_pb[(size_t)c * CX + q + 2], v.z); atomicAdd(&g_pb[(size_t)c * CX + q + 3], v.w);
        if ((i & 31) == 0) g_has[c] = 1;
    }
}

__global__ void k_xout(float* out) {
    int i = blockIdx.x * blockDim.x + threadIdx.x;
    if (i >= NN * 32) return;
    int cl = i >> 5, q = (i & 31) * 4;
    int h = g_has[cl];
    float4 a = *(float4*)&g_pa[(size_t)cl * CX + q];
    float4 b = *(float4*)&g_pb[(size_t)cl * CX + q];
    float4 o = h ? b : a;
    *(float4*)&out[OFF_X + (size_t)cl * CX + q] = o;
    if ((i & 31) == 0) out[OFF_BATCH + cl] = (float)g_bout[cl];
    if (cl < g_rb[BBG]) {
        int bg = g_bout[cl];
        atomicAdd(&g_xg[bg * CX + q], o.x); atomicAdd(&g_xg[bg * CX + q + 1], o.y);
        atomicAdd(&g_xg[bg * CX + q + 2], o.z); atomicAdd(&g_xg[bg * CX + q + 3], o.w);
    }
}

__global__ void k_bnxg(const float* __restrict__ g, const float* __restrict__ b, float* out) {
    int c = threadIdx.x;
    if (c >= CX) return;
    double s = 0.0, q = 0.0;
    for (int i = 0; i < BBG; i++) { double v = g_xg[i * CX + c]; s += v; q += v * v; }
    double mu = s / BBG, var = q / BBG - mu * mu;
    float a = g[c] / (float)sqrt(var + 1e-5);
    float d = b[c] - (float)mu * a;
    for (int i = 0; i < BBG; i++) out[OFF_XG + i * CX + c] = g_xg[i * CX + c] * a + d;
}

// ---------------- emit edge_index_out per unique key ----------------
__global__ void k_eio(float* out) {
    int g = blockIdx.x, t = threadIdx.x;
    int U = g_ucnt[g], ub = g_ub[g];
    for (int p = t; p < U; p += 256) {
        u32 key = g_ukeys[g * SORTN + p];
        int seg = ub + p;
        out[OFF_EIO + seg] = (float)(key / (u32)NN);
        out[OFF_EIO + EE + seg] = (float)(key % (u32)NN);
    }
}

// ---------------- emit attr sums: thread per (edge, float4-chunk) --------------
__global__ void k_emit2(const int* __restrict__ row, float* out) {
    int i = blockIdx.x * 256 + threadIdx.x;
    if (i >= EE * 8) return;
    int e = i >> 3, q = (i & 7) * 4;
    if (g_sel[e]) return;
    int g = row[e] / BLKG;
    int seg = g_ub[g] + g_erank[e];
    float4 a = *(const float4*)&g_ea[e * CE + q];
    float* dst = &out[OFF_ATTR + (size_t)seg * CE + q];
    atomicAdd(dst, a.x); atomicAdd(dst + 1, a.y);
    atomicAdd(dst + 2, a.z); atomicAdd(dst + 3, a.w);
}

extern "C" void kernel_launch(void* const* d_in, const int* in_sizes, int n_in,
                              void* d_out, int out_size) {
    const float* x = (const float*)d_in[0];
    const int* ei = (const int*)d_in[1];
    const float* eattr = (const float*)d_in[2];
    const float* S = (const float*)d_in[4];
    const float* We = (const float*)d_in[5];
    const float* be = (const float*)d_in[6];
    const float* bn_e_g = (const float*)d_in[7];
    const float* bn_e_b = (const float*)d_in[8];
    const float* Wedge = (const float*)d_in[9];
    const float* eps = (const float*)d_in[10];
    const float* W1 = (const float*)d_in[11];
    const float* b1 = (const float*)d_in[12];
    const float* W2 = (const float*)d_in[13];
    const float* b2 = (const float*)d_in[14];
    const float* bn_g = (const float*)d_in[15];
    const float* bn_b = (const float*)d_in[16];
    float* out = (float*)d_out;
    const int* row = ei;
    const int* col = ei + EE;

    cudaFuncSetAttribute(k_unique, cudaFuncAttributeMaxDynamicSharedMemorySize, 3 * HSH * 4);
    cudaFuncSetAttribute(k_cc, cudaFuncAttributeMaxDynamicSharedMemorySize, HSH * 4);

    k_init<<<(EE * CE + 255) / 256, 256>>>(out);
    k_rowstart<<<(NN + 256) / 256, 256>>>(row);
    k_rev<<<(EE + 255) / 256, 256>>>(row, col);
    k_nodesum<<<(NN * 32 + 255) / 256, 256>>>(eattr);
    k_lin<<<(EE + 255) / 256, 256>>>(row, eattr, We, be);
    k_bnstats<<<512, 256>>>();
    k_bnfin<<<1, 32>>>(bn_e_g, bn_e_b, S);
    k_score<<<(EE + 255) / 256, 256>>>(row, S);
    k_gmean<<<1, 64>>>();
    k_sel<<<(EE + 255) / 256, 256>>>(row);
    k_cc<<<BBG, 768, HSH * 4>>>(row, col);
    k_scan64<<<1, 32>>>();
    k_comp<<<BBG, 1024>>>();
    k_unique<<<BBG, 1024, 3 * HSH * 4>>>(row, col);
    k_uscan<<<1, 32>>>();
    k_msg2<<<(NN * 32 + 255) / 256, 256>>>(x, Wedge, eps, col);
    k_gemm<<<NN / 64, 256>>>(W1, b1, 0);
    k_gemm<<<NN / 64, 256>>>(W2, b2, 1);
    k_pool<<<(NN * 32 + 255) / 256, 256>>>(x);
    k_xout<<<(NN * 32 + 255) / 256, 256>>>(out);
    k_bnxg<<<1, 128>>>(bn_g, bn_b, out);
    k_eio<<<BBG, 256>>>(out);
    k_emit2<<<(EE * 8 + 255) / 256, 256>>>(row, out);
}

// round 8
// speedup vs baseline: 8.6134x; 1.4039x over previous
#include <cuda_runtime.h>
#include <math.h>

#define NN 46080
#define BBG 64
#define BLKG 720
#define EE 400000
#define CX 128
#define CE 32
#define SORTN 16384
#define HSH 16384
#define OFF_X 0
#define OFF_EIO 5898240
#define OFF_ATTR 6698240
#define OFF_BATCH 19498240
#define OFF_XG 19544320

typedef unsigned long long u64;
typedef unsigned int u32;

__device__ int g_rs[NN + 1];
__device__ int g_rev[EE];
__device__ float g_ns[NN * CE];
__device__ float g_ea[EE * CE];
__device__ double g_bnstat[2 * CE];
__device__ float g_bna[CE], g_bnd[CE];
__device__ float g_snr;
__device__ float g_score[EE];
__device__ double g_gsum[BBG];
__device__ float g_gmean[BBG];
__device__ unsigned char g_sel[EE];
__device__ int g_xmask[NN];
__device__ int g_lab[NN];
__device__ int g_repcnt[BBG];
__device__ int g_rb[BBG + 1];
__device__ int g_comp[NN];
__device__ int g_bout[NN];
__device__ float g_h[NN * CX];
__device__ float g_t1[NN * CX];
__device__ float g_xc[NN * CX];
__device__ float g_pa[NN * CX];
__device__ float g_pb[NN * CX];
__device__ int g_has[NN];
__device__ float g_xg[BBG * CX];
__device__ u32 g_ukeys[BBG * SORTN];
__device__ int g_erank[EE];
__device__ int g_ucnt[BBG];
__device__ int g_ub[BBG + 1];

// ---------------- eio = -1 fill (rest of init via cudaMemsetAsync) -------------
__global__ void k_fill(float* out) {
    int i = blockIdx.x * blockDim.x + threadIdx.x;
    if (i < 2 * EE) out[OFF_EIO + i] = -1.f;
}

// ---------------- rowstart via binary search ----------------
__global__ void k_rowstart(const int* __restrict__ row) {
    int r = blockIdx.x * blockDim.x + threadIdx.x;
    if (r > NN) return;
    int lo = 0, hi = EE;
    while (lo < hi) { int m = (lo + hi) >> 1; if (row[m] < r) lo = m + 1; else hi = m; }
    g_rs[r] = lo;
}

// ---------------- reverse edge index ----------------
__global__ void k_rev(const int* __restrict__ row, const int* __restrict__ col) {
    int e = blockIdx.x * blockDim.x + threadIdx.x;
    if (e >= EE) return;
    int t = col[e], v = row[e];
    int lo = g_rs[t], hi = g_rs[t + 1];
    while (lo < hi) { int m = (lo + hi) >> 1; if (col[m] < v) lo = m + 1; else hi = m; }
    g_rev[e] = lo;
}

// ---------------- nodesum[n][c] = sum over in-edges of attr (via rev) ----------
__global__ void k_nodesum(const float* __restrict__ eattr) {
    int w = (blockIdx.x * blockDim.x + threadIdx.x) >> 5;
    int l = threadIdx.x & 31;
    if (w >= NN) return;
    float s = 0.f;
    for (int e = g_rs[w]; e < g_rs[w + 1]; e++) s += eattr[g_rev[e] * CE + l];
    g_ns[w * CE + l] = s;
}

// ---------------- raw linear: ea = (ns[row]+attr) @ We + be --------------------
__global__ void k_lin(const int* __restrict__ row, const float* __restrict__ eattr,
                      const float* __restrict__ We, const float* __restrict__ be) {
    __shared__ float Ws[CE * CE], bs[CE];
    int t = threadIdx.x;
    for (int i = t; i < CE * CE; i += 256) Ws[i] = We[i];
    if (t < CE) bs[t] = be[t];
    __syncthreads();
    int e = blockIdx.x * 256 + t;
    if (e >= EE) return;
    float in[CE], o[CE];
    int r = row[e];
    #pragma unroll
    for (int k = 0; k < CE; k += 4) {
        float4 a = *(const float4*)&g_ns[r * CE + k];
        float4 b = *(const float4*)&eattr[e * CE + k];
        in[k] = a.x + b.x; in[k+1] = a.y + b.y; in[k+2] = a.z + b.z; in[k+3] = a.w + b.w;
    }
    #pragma unroll 4
    for (int j = 0; j < CE; j++) {
        float a = bs[j];
        #pragma unroll
        for (int k = 0; k < CE; k++) a += in[k] * Ws[k * CE + j];
        o[j] = a;
    }
    #pragma unroll
    for (int j = 0; j < CE; j += 4)
        *(float4*)&g_ea[e * CE + j] = make_float4(o[j], o[j+1], o[j+2], o[j+3]);
}

// ---------------- BN statistics: coalesced warp pass over g_ea -----------------
__global__ void k_bnstats() {
    int w = (blockIdx.x * blockDim.x + threadIdx.x) >> 5;
    int l = threadIdx.x & 31;
    int nw = (gridDim.x * blockDim.x) >> 5;
    double s = 0.0, q = 0.0;
    for (int e = w; e < EE; e += nw) {
        float v = g_ea[e * CE + l];
        s += v; q += (double)v * v;
    }
    atomicAdd(&g_bnstat[l], s);
    atomicAdd(&g_bnstat[CE + l], q);
}

// ---------------- BN finalize + S norm (merged) ----------------
__global__ void k_bnfin(const float* __restrict__ g, const float* __restrict__ b,
                        const float* __restrict__ S) {
    int j = threadIdx.x;
    float v = S[j] * S[j];
    for (int o = 16; o; o >>= 1) v += __shfl_down_sync(~0u, v, o);
    if (j == 0) g_snr = sqrtf(v);
    double mu = g_bnstat[j] / (double)EE;
    double var = g_bnstat[CE + j] / (double)EE - mu * mu;
    float a = g[j] / (float)sqrt(var + 1e-5);
    g_bna[j] = a; g_bnd[j] = b[j] - (float)mu * a;
}

// ---------------- score (BN+ReLU fused, float4) + per-graph sums (double) ------
__global__ void k_score(const int* __restrict__ row, const float* __restrict__ S) {
    __shared__ double sloc[2];
    __shared__ float Ss[CE], Ba[CE], Bd[CE];
    int t = threadIdx.x;
    if (t < 2) sloc[t] = 0.0;
    if (t < CE) { Ss[t] = S[t]; Ba[t] = g_bna[t]; Bd[t] = g_bnd[t]; }
    __syncthreads();
    int e = blockIdx.x * 256 + t;
    int g0 = row[min(blockIdx.x * 256, EE - 1)] / BLKG;
    if (e < EE) {
        int re = g_rev[e];
        float z = 0.f;
        #pragma unroll
        for (int k = 0; k < CE; k += 4) {
            float4 a = *(const float4*)&g_ea[e * CE + k];
            float4 b = *(const float4*)&g_ea[re * CE + k];
            z += (fmaxf(a.x * Ba[k]   + Bd[k],   0.f) + fmaxf(b.x * Ba[k]   + Bd[k],   0.f)) * Ss[k];
            z += (fmaxf(a.y * Ba[k+1] + Bd[k+1], 0.f) + fmaxf(b.y * Ba[k+1] + Bd[k+1], 0.f)) * Ss[k+1];
            z += (fmaxf(a.z * Ba[k+2] + Bd[k+2], 0.f) + fmaxf(b.z * Ba[k+2] + Bd[k+2], 0.f)) * Ss[k+2];
            z += (fmaxf(a.w * Ba[k+3] + Bd[k+3], 0.f) + fmaxf(b.w * Ba[k+3] + Bd[k+3], 0.f)) * Ss[k+3];
        }
        float s = 1.f / (1.f + expf(-z / g_snr));
        g_score[e] = s;
        int gg = row[e] / BLKG;
        atomicAdd(&sloc[gg == g0 ? 0 : 1], (double)s);
    }
    __syncthreads();
    if (t == 0) {
        atomicAdd(&g_gsum[g0], sloc[0]);
        int g1 = row[min(blockIdx.x * 256 + 255, EE - 1)] / BLKG;
        if (g1 != g0 && sloc[1] != 0.0) atomicAdd(&g_gsum[g1], sloc[1]);
    }
}

__global__ void k_gmean() {
    int g = threadIdx.x;
    if (g >= BBG) return;
    int c = g_rs[(g + 1) * BLKG] - g_rs[g * BLKG];
    g_gmean[g] = c ? (float)(g_gsum[g] / (double)c) : 0.f;
}

// ---------------- CC per graph, with fused selection ----------------
__global__ void k_cc(const int* __restrict__ row, const int* __restrict__ col) {
    extern __shared__ u32 eb[];         // packed selected edges r<<10 | c
    __shared__ int lab[BLKG];
    __shared__ int chg, rc, ecnt;
    int g = blockIdx.x, t = threadIdx.x;
    int base = g * BLKG;
    int e0 = g_rs[base], e1 = g_rs[base + BLKG];
    for (int i = t; i < BLKG; i += blockDim.x) lab[i] = i;
    if (t == 0) { chg = 1; rc = 0; ecnt = 0; }
    __syncthreads();
    float gm = g_gmean[g];
    for (int e = e0 + t; e < e1; e += blockDim.x) {
        float s = g_score[e];
        unsigned char sl = (s <= 0.5f) && (s < gm);
        g_sel[e] = sl;
        if (sl) {
            g_xmask[row[e]] = 1;
            int p = atomicAdd(&ecnt, 1);
            eb[p] = ((u32)(row[e] - base) << 10) | (u32)(col[e] - base);
        }
    }
    __syncthreads();
    int ne = ecnt;
    for (int it = 0; it < 256 && chg; it++) {
        __syncthreads();
        if (t == 0) chg = 0;
        __syncthreads();
        for (int i = t; i < ne; i += blockDim.x) {
            u32 p = eb[i];
            int r = p >> 10, c = p & 1023;
            int lr = lab[r], lc = lab[c];
            if (lr < lc) { if (atomicMin(&lab[c], lr) > lr) chg = 1; }
            else if (lc < lr) { if (atomicMin(&lab[r], lc) > lc) chg = 1; }
        }
        __syncthreads();
        for (int i = t; i < BLKG; i += blockDim.x) {
            int l = lab[i], ll = lab[l];
            if (ll < l) { lab[i] = ll; chg = 1; }
        }
        __syncthreads();
    }
    for (int i = t; i < BLKG; i += blockDim.x) {
        g_lab[base + i] = lab[i];
        if (lab[i] == i) atomicAdd(&rc, 1);
    }
    __syncthreads();
    if (t == 0) g_repcnt[g] = rc;
}

__global__ void k_scan64() {
    if (threadIdx.x == 0) {
        int a = 0;
        for (int g = 0; g < BBG; g++) { g_rb[g] = a; a += g_repcnt[g]; }
        g_rb[BBG] = a;
    }
}

__global__ void k_comp() {
    __shared__ int s[1024];
    int g = blockIdx.x, t = threadIdx.x;
    int base = g * BLKG;
    s[t] = (t < BLKG && g_lab[base + t] == t) ? 1 : 0;
    __syncthreads();
    for (int off = 1; off < 1024; off <<= 1) {
        int v = (t >= off) ? s[t - off] : 0;
        __syncthreads(); s[t] += v; __syncthreads();
    }
    if (t < BLKG) {
        int c = g_rb[g] + s[g_lab[base + t]] - 1;
        g_comp[base + t] = c;
        g_bout[c] = g;
    }
}

// ---------------- unique coalesce keys via smem hash + tiny sort ----------------
__global__ void k_unique(const int* __restrict__ row, const int* __restrict__ col) {
    extern __shared__ u32 sh[];
    u32* hkey  = sh;
    u32* hrank = sh + HSH;
    u32* ulist = sh + 2 * HSH;
    __shared__ int part[1024];
    int g = blockIdx.x, t = threadIdx.x;
    int e0 = g_rs[g * BLKG], e1 = g_rs[(g + 1) * BLKG];
    for (int i = t; i < HSH; i += 1024) hkey[i] = 0xFFFFFFFFu;
    __syncthreads();
    for (int e = e0 + t; e < e1; e += 1024) {
        if (g_sel[e]) continue;
        u32 key = (u32)g_comp[row[e]] * (u32)NN + (u32)g_comp[col[e]];
        u32 h = (key * 2654435761u) & (HSH - 1);
        while (true) {
            u32 old = atomicCAS(&hkey[h], 0xFFFFFFFFu, key);
            if (old == 0xFFFFFFFFu || old == key) break;
            h = (h + 1) & (HSH - 1);
        }
        g_erank[e] = (int)h;
    }
    __syncthreads();
    int i0 = t * 16, run = 0;
    for (int j = 0; j < 16; j++) run += (hkey[i0 + j] != 0xFFFFFFFFu);
    part[t] = run;
    __syncthreads();
    for (int off = 1; off < 1024; off <<= 1) {
        int v = (t >= off) ? part[t - off] : 0;
        __syncthreads(); part[t] += v; __syncthreads();
    }
    int base = t ? part[t - 1] : 0;
    int w = 0;
    for (int j = 0; j < 16; j++) {
        u32 k2 = hkey[i0 + j];
        if (k2 != 0xFFFFFFFFu) ulist[base + w++] = k2;
    }
    int U = part[1023];
    if (t == 0) g_ucnt[g] = U;
    __syncthreads();
    int P = 2; while (P < U) P <<= 1;
    for (int i = U + t; i < P; i += 1024) ulist[i] = 0xFFFFFFFFu;
    __syncthreads();
    for (u32 k = 2; k <= (u32)P; k <<= 1)
        for (u32 j = k >> 1; j; j >>= 1) {
            for (u32 i = t; i < (u32)P; i += 1024) {
                u32 ixj = i ^ j;
                if (ixj > i) {
                    u32 a = ulist[i], b = ulist[ixj];
                    bool up = ((i & k) == 0);
                    if ((a > b) == up) { ulist[i] = b; ulist[ixj] = a; }
                }
            }
            __syncthreads();
        }
    for (int p = t; p < U; p += 1024) {
        u32 key = ulist[p];
        u32 h = (key * 2654435761u) & (HSH - 1);
        while (hkey[h] != key) h = (h + 1) & (HSH - 1);
        hrank[h] = (u32)p;
        g_ukeys[g * SORTN + p] = key;
    }
    __syncthreads();
    for (int e = e0 + t; e < e1; e += 1024) {
        if (g_sel[e]) continue;
        g_erank[e] = (int)hrank[g_erank[e]];
    }
}

__global__ void k_uscan() {
    if (threadIdx.x == 0) {
        int a = 0;
        for (int g = 0; g < BBG; g++) { g_ub[g] = a; a += g_ucnt[g]; }
        g_ub[BBG] = a;
    }
}

// ---------------- EGIN message + aggregate (bn/score fused) -> g_h -------------
__global__ void k_msg2(const float* __restrict__ x, const float* __restrict__ Wedge,
                       const float* __restrict__ eps, const int* __restrict__ col) {
    __shared__ float Ws[CE * CX];
    __shared__ float Ba[CE], Bd[CE];
    int t = threadIdx.x;
    for (int i = t; i < CE * CX; i += 256) Ws[i] = Wedge[i];
    if (t < CE) { Ba[t] = g_bna[t]; Bd[t] = g_bnd[t]; }
    __syncthreads();
    int n = (blockIdx.x * 256 + t) >> 5;
    int l = t & 31;
    if (n >= NN) return;
    float4 agg = make_float4(0.f, 0.f, 0.f, 0.f);
    for (int e = g_rs[n]; e < g_rs[n + 1]; e++) {
        if (!g_sel[e]) continue;
        float sc = g_score[e];
        float4 m = make_float4(0.f, 0.f, 0.f, 0.f);
        #pragma unroll 8
        for (int k = 0; k < CE; k++) {
            float ek = fmaxf(__ldg(&g_ea[e * CE + k]) * Ba[k] + Bd[k], 0.f) * sc;
            float4 w = *(const float4*)&Ws[k * CX + l * 4];
            m.x += ek * w.x; m.y += ek * w.y; m.z += ek * w.z; m.w += ek * w.w;
        }
        const float4 xc = *(const float4*)&x[(size_t)col[e] * CX + l * 4];
        agg.x += fmaxf(m.x + xc.x, 0.f); agg.y += fmaxf(m.y + xc.y, 0.f);
        agg.z += fmaxf(m.z + xc.z, 0.f); agg.w += fmaxf(m.w + xc.w, 0.f);
    }
    float ep = 1.f + eps[0];
    const float4 xn = *(const float4*)&x[(size_t)n * CX + l * 4];
    float4 h = make_float4(ep * xn.x + agg.x, ep * xn.y + agg.y,
                           ep * xn.z + agg.z, ep * xn.w + agg.w);
    *(float4*)&g_h[(size_t)n * CX + l * 4] = h;
}

// ---------------- GEMM 128x128 tile, 8x8 per thread ----------------------------
__global__ void k_gemm(const float* __restrict__ W, const float* __restrict__ bias,
                       int which) {
    const float* A = which ? g_t1 : g_h;
    float* C = which ? g_xc : g_t1;
    int relu = (which == 0);
    __shared__ float As[8][128];
    __shared__ float Bs[8][128];
    int t = threadIdx.x;
    int m0 = blockIdx.x * 128;
    int tx = t & 15, ty = t >> 4;
    float acc[8][8];
    #pragma unroll
    for (int i = 0; i < 8; i++)
        #pragma unroll
        for (int j = 0; j < 8; j++) acc[i][j] = 0.f;
    int lm = t >> 1, lk = (t & 1) * 4;
    int bk = t >> 5, bn = (t & 31) * 4;
    for (int k0 = 0; k0 < CX; k0 += 8) {
        float4 av = *(const float4*)&A[(size_t)(m0 + lm) * CX + k0 + lk];
        As[lk + 0][lm] = av.x; As[lk + 1][lm] = av.y;
        As[lk + 2][lm] = av.z; As[lk + 3][lm] = av.w;
        *(float4*)&Bs[bk][bn] = *(const float4*)&W[(size_t)(k0 + bk) * CX + bn];
        __syncthreads();
        #pragma unroll
        for (int kk = 0; kk < 8; kk++) {
            float4 a0 = *(float4*)&As[kk][ty * 8];
            float4 a1 = *(float4*)&As[kk][ty * 8 + 4];
            float4 b0 = *(float4*)&Bs[kk][tx * 8];
            float4 b1 = *(float4*)&Bs[kk][tx * 8 + 4];
            float am[8] = {a0.x, a0.y, a0.z, a0.w, a1.x, a1.y, a1.z, a1.w};
            float bv[8] = {b0.x, b0.y, b0.z, b0.w, b1.x, b1.y, b1.z, b1.w};
            #pragma unroll
            for (int i = 0; i < 8; i++)
                #pragma unroll
                for (int j = 0; j < 8; j++) acc[i][j] += am[i] * bv[j];
        }
        __syncthreads();
    }
    #pragma unroll
    for (int i = 0; i < 8; i++) {
        int m = m0 + ty * 8 + i;
        #pragma unroll
        for (int j = 0; j < 8; j += 4) {
            float4 bb = *(const float4*)&bias[tx * 8 + j];
            float4 o = make_float4(acc[i][j] + bb.x, acc[i][j+1] + bb.y,
                                   acc[i][j+2] + bb.z, acc[i][j+3] + bb.w);
            if (relu) {
                o.x = fmaxf(o.x, 0.f); o.y = fmaxf(o.y, 0.f);
                o.z = fmaxf(o.z, 0.f); o.w = fmaxf(o.w, 0.f);
            }
            *(float4*)&C[(size_t)m * CX + tx * 8 + j] = o;
        }
    }
}

// ---------------- pooling ----------------
__global__ void k_pool(const float* __restrict__ x) {
    int i = blockIdx.x * blockDim.x + threadIdx.x;
    if (i >= NN * 32) return;
    int n = i >> 5, q = (i & 31) * 4;
    int c = g_comp[n];
    if (g_xmask[n]) {
        float4 v = *(const float4*)&g_xc[(size_t)n * CX + q];
        atomicAdd(&g_pa[(size_t)c * CX + q], v.x); atomicAdd(&g_pa[(size_t)c * CX + q + 1], v.y);
        atomicAdd(&g_pa[(size_t)c * CX + q + 2], v.z); atomicAdd(&g_pa[(size_t)c * CX + q + 3], v.w);
    } else {
        float4 v = *(const float4*)&x[(size_t)n * CX + q];
        atomicAdd(&g_pb[(size_t)c * CX + q], v.x); atomicAdd(&g_pb[(size_t)c * CX + q + 1], v.y);
        atomicAdd(&g_pb[(size_t)c * CX + q + 2], v.z); atomicAdd(&g_pb[(size_t)c * CX + q + 3], v.w);
        if ((i & 31) == 0) g_has[c] = 1;
    }
}

__global__ void k_xout(float* out) {
    int i = blockIdx.x * blockDim.x + threadIdx.x;
    if (i >= NN * 32) return;
    int cl = i >> 5, q = (i & 31) * 4;
    int h = g_has[cl];
    float4 a = *(float4*)&g_pa[(size_t)cl * CX + q];
    float4 b = *(float4*)&g_pb[(size_t)cl * CX + q];
    float4 o = h ? b : a;
    *(float4*)&out[OFF_X + (size_t)cl * CX + q] = o;
    if ((i & 31) == 0) out[OFF_BATCH + cl] = (float)g_bout[cl];
    if (cl < g_rb[BBG]) {
        int bg = g_bout[cl];
        atomicAdd(&g_xg[bg * CX + q], o.x); atomicAdd(&g_xg[bg * CX + q + 1], o.y);
        atomicAdd(&g_xg[bg * CX + q + 2], o.z); atomicAdd(&g_xg[bg * CX + q + 3], o.w);
    }
}

__global__ void k_bnxg(const float* __restrict__ g, const float* __restrict__ b, float* out) {
    int c = threadIdx.x;
    if (c >= CX) return;
    double s = 0.0, q = 0.0;
    for (int i = 0; i < BBG; i++) { double v = g_xg[i * CX + c]; s += v; q += v * v; }
    double mu = s / BBG, var = q / BBG - mu * mu;
    float a = g[c] / (float)sqrt(var + 1e-5);
    float d = b[c] - (float)mu * a;
    for (int i = 0; i < BBG; i++) out[OFF_XG + i * CX + c] = g_xg[i * CX + c] * a + d;
}

// ---------------- emit edge_index_out per unique key ----------------
__global__ void k_eio(float* out) {
    int g = blockIdx.x, t = threadIdx.x;
    int U = g_ucnt[g], ub = g_ub[g];
    for (int p = t; p < U; p += 256) {
        u32 key = g_ukeys[g * SORTN + p];
        int seg = ub + p;
        out[OFF_EIO + seg] = (float)(key / (u32)NN);
        out[OFF_EIO + EE + seg] = (float)(key % (u32)NN);
    }
}

// ---------------- emit attr: lane=channel, warp walks 8 edges, run-reduce ------
__global__ void k_emit2(const int* __restrict__ row, float* out) {
    __shared__ float Ba[CE], Bd[CE];
    int t = threadIdx.x;
    if (t < CE) { Ba[t] = g_bna[t]; Bd[t] = g_bnd[t]; }
    __syncthreads();
    int wid = (blockIdx.x * 256 + t) >> 5;
    int l = t & 31;
    int e0 = wid * 8;
    float acc = 0.f;
    int cur = -1;
    for (int j = 0; j < 8; j++) {
        int e = e0 + j;
        if (e >= EE) break;
        if (g_sel[e]) continue;
        int g = row[e] / BLKG;
        int seg = g_ub[g] + g_erank[e];
        float v = fmaxf(g_ea[e * CE + l] * Ba[l] + Bd[l], 0.f) * g_score[e];
        if (seg != cur) {
            if (cur >= 0) atomicAdd(&out[OFF_ATTR + (size_t)cur * CE + l], acc);
            cur = seg; acc = 0.f;
        }
        acc += v;
    }
    if (cur >= 0) atomicAdd(&out[OFF_ATTR + (size_t)cur * CE + l], acc);
}

extern "C" void kernel_launch(void* const* d_in, const int* in_sizes, int n_in,
                              void* d_out, int out_size) {
    const float* x = (const float*)d_in[0];
    const int* ei = (const int*)d_in[1];
    const float* eattr = (const float*)d_in[2];
    const float* S = (const float*)d_in[4];
    const float* We = (const float*)d_in[5];
    const float* be = (const float*)d_in[6];
    const float* bn_e_g = (const float*)d_in[7];
    const float* bn_e_b = (const float*)d_in[8];
    const float* Wedge = (const float*)d_in[9];
    const float* eps = (const float*)d_in[10];
    const float* W1 = (const float*)d_in[11];
    const float* b1 = (const float*)d_in[12];
    const float* W2 = (const float*)d_in[13];
    const float* b2 = (const float*)d_in[14];
    const float* bn_g = (const float*)d_in[15];
    const float* bn_b = (const float*)d_in[16];
    float* out = (float*)d_out;
    const int* row = ei;
    const int* col = ei + EE;

    cudaFuncSetAttribute(k_unique, cudaFuncAttributeMaxDynamicSharedMemorySize, 3 * HSH * 4);
    cudaFuncSetAttribute(k_cc, cudaFuncAttributeMaxDynamicSharedMemorySize, HSH * 4);

    // bulk zeroing via memset nodes
    void *pa, *pb, *xg, *bnstat, *gsum, *xmask, *has, *bout;
    cudaGetSymbolAddress(&pa, g_pa);
    cudaGetSymbolAddress(&pb, g_pb);
    cudaGetSymbolAddress(&xg, g_xg);
    cudaGetSymbolAddress(&bnstat, g_bnstat);
    cudaGetSymbolAddress(&gsum, g_gsum);
    cudaGetSymbolAddress(&xmask, g_xmask);
    cudaGetSymbolAddress(&has, g_has);
    cudaGetSymbolAddress(&bout, g_bout);
    cudaMemsetAsync(out + OFF_ATTR, 0, (size_t)EE * CE * 4);
    cudaMemsetAsync(pa, 0, (size_t)NN * CX * 4);
    cudaMemsetAsync(pb, 0, (size_t)NN * CX * 4);
    cudaMemsetAsync(xg, 0, (size_t)BBG * CX * 4);
    cudaMemsetAsync(bnstat, 0, 2 * CE * 8);
    cudaMemsetAsync(gsum, 0, BBG * 8);
    cudaMemsetAsync(xmask, 0, NN * 4);
    cudaMemsetAsync(has, 0, NN * 4);
    cudaMemsetAsync(bout, 0, NN * 4);

    k_fill<<<(2 * EE + 255) / 256, 256>>>(out);
    k_rowstart<<<(NN + 256) / 256, 256>>>(row);
    k_rev<<<(EE + 255) / 256, 256>>>(row, col);
    k_nodesum<<<(NN * 32 + 255) / 256, 256>>>(eattr);
    k_lin<<<(EE + 255) / 256, 256>>>(row, eattr, We, be);
    k_bnstats<<<512, 256>>>();
    k_bnfin<<<1, 32>>>(bn_e_g, bn_e_b, S);
    k_score<<<(EE + 255) / 256, 256>>>(row, S);
    k_gmean<<<1, 64>>>();
    k_cc<<<BBG, 768, HSH * 4>>>(row, col);
    k_scan64<<<1, 32>>>();
    k_comp<<<BBG, 1024>>>();
    k_unique<<<BBG, 1024, 3 * HSH * 4>>>(row, col);
    k_uscan<<<1, 32>>>();
    k_msg2<<<(NN * 32 + 255) / 256, 256>>>(x, Wedge, eps, col);
    k_gemm<<<NN / 128, 256>>>(W1, b1, 0);
    k_gemm<<<NN / 128, 256>>>(W2, b2, 1);
    k_pool<<<(NN * 32 + 255) / 256, 256>>>(x);
    k_xout<<<(NN * 32 + 255) / 256, 256>>>(out);
    k_bnxg<<<1, 128>>>(bn_g, bn_b, out);
    k_eio<<<BBG, 256>>>(out);
    k_emit2<<<(EE / 8 * 32 + 255) / 256, 256>>>(row, out);
}

// round 9
// speedup vs baseline: 8.8639x; 1.0291x over previous
#include <cuda_runtime.h>
#include <math.h>
#include <mma.h>

using namespace nvcuda;

#define NN 46080
#define BBG 64
#define BLKG 720
#define EE 400000
#define CX 128
#define CE 32
#define SORTN 16384
#define HSH 16384
#define OFF_X 0
#define OFF_EIO 5898240
#define OFF_ATTR 6698240
#define OFF_BATCH 19498240
#define OFF_XG 19544320

typedef unsigned long long u64;
typedef unsigned int u32;

__device__ int g_rs[NN + 1];
__device__ int g_rev[EE];
__device__ float g_ns[NN * CE];
__device__ float g_ea[EE * CE];
__device__ double g_bnstat[2 * CE];
__device__ float g_bna[CE], g_bnd[CE];
__device__ float g_snr;
__device__ float g_score[EE];
__device__ double g_gsum[BBG];
__device__ float g_gmean[BBG];
__device__ unsigned char g_sel[EE];
__device__ int g_xmask[NN];
__device__ int g_lab[NN];
__device__ int g_repcnt[BBG];
__device__ int g_rb[BBG + 1];
__device__ int g_comp[NN];
__device__ int g_bout[NN];
__device__ float g_h[NN * CX];
__device__ float g_xc[NN * CX];
__device__ float g_pa[NN * CX];
__device__ float g_pb[NN * CX];
__device__ int g_has[NN];
__device__ float g_xg[BBG * CX];
__device__ u32 g_ukeys[BBG * SORTN];
__device__ int g_erank[EE];
__device__ int g_ucnt[BBG];
__device__ int g_ub[BBG + 1];

// ---------------- eio = -1 fill ----------------
__global__ void k_fill(float* out) {
    int i = blockIdx.x * blockDim.x + threadIdx.x;
    if (i < 2 * EE) out[OFF_EIO + i] = -1.f;
}

// ---------------- rowstart via binary search ----------------
__global__ void k_rowstart(const int* __restrict__ row) {
    int r = blockIdx.x * blockDim.x + threadIdx.x;
    if (r > NN) return;
    int lo = 0, hi = EE;
    while (lo < hi) { int m = (lo + hi) >> 1; if (row[m] < r) lo = m + 1; else hi = m; }
    g_rs[r] = lo;
}

// ---------------- reverse edge index ----------------
__global__ void k_rev(const int* __restrict__ row, const int* __restrict__ col) {
    int e = blockIdx.x * blockDim.x + threadIdx.x;
    if (e >= EE) return;
    int t = col[e], v = row[e];
    int lo = g_rs[t], hi = g_rs[t + 1];
    while (lo < hi) { int m = (lo + hi) >> 1; if (col[m] < v) lo = m + 1; else hi = m; }
    g_rev[e] = lo;
}

// ---------------- nodesum ----------------
__global__ void k_nodesum(const float* __restrict__ eattr) {
    int w = (blockIdx.x * blockDim.x + threadIdx.x) >> 5;
    int l = threadIdx.x & 31;
    if (w >= NN) return;
    float s = 0.f;
    for (int e = g_rs[w]; e < g_rs[w + 1]; e++) s += eattr[g_rev[e] * CE + l];
    g_ns[w * CE + l] = s;
}

// ---------------- linear + fused BN stats (smem transpose reduce) --------------
__global__ void k_lin(const int* __restrict__ row, const float* __restrict__ eattr,
                      const float* __restrict__ We, const float* __restrict__ be) {
    __shared__ float Ws[CE * CE], bs[CE];
    __shared__ float tr[256 * 33];
    int t = threadIdx.x;
    for (int i = t; i < CE * CE; i += 256) Ws[i] = We[i];
    if (t < CE) bs[t] = be[t];
    __syncthreads();
    int e = blockIdx.x * 256 + t;
    bool ok = (e < EE);
    float in[CE], o[CE];
    if (ok) {
        int r = row[e];
        #pragma unroll
        for (int k = 0; k < CE; k += 4) {
            float4 a = *(const float4*)&g_ns[r * CE + k];
            float4 b = *(const float4*)&eattr[e * CE + k];
            in[k] = a.x + b.x; in[k+1] = a.y + b.y; in[k+2] = a.z + b.z; in[k+3] = a.w + b.w;
        }
    } else {
        #pragma unroll
        for (int k = 0; k < CE; k++) in[k] = 0.f;
    }
    #pragma unroll 4
    for (int j = 0; j < CE; j++) {
        float a = ok ? bs[j] : 0.f;
        #pragma unroll
        for (int k = 0; k < CE; k++) a += in[k] * Ws[k * CE + j];
        o[j] = a;
        tr[t * 33 + j] = a;
    }
    if (ok) {
        #pragma unroll
        for (int j = 0; j < CE; j += 4)
            *(float4*)&g_ea[e * CE + j] = make_float4(o[j], o[j+1], o[j+2], o[j+3]);
    }
    __syncthreads();
    if (t < CE) {
        double s = 0.0, q = 0.0;
        for (int r = 0; r < 256; r++) {
            float v = tr[r * 33 + t];
            s += v; q += (double)v * v;
        }
        atomicAdd(&g_bnstat[t], s);
        atomicAdd(&g_bnstat[CE + t], q);
    }
}

// ---------------- BN finalize + S norm ----------------
__global__ void k_bnfin(const float* __restrict__ g, const float* __restrict__ b,
                        const float* __restrict__ S) {
    int j = threadIdx.x;
    float v = S[j] * S[j];
    for (int o = 16; o; o >>= 1) v += __shfl_down_sync(~0u, v, o);
    if (j == 0) g_snr = sqrtf(v);
    double mu = g_bnstat[j] / (double)EE;
    double var = g_bnstat[CE + j] / (double)EE - mu * mu;
    float a = g[j] / (float)sqrt(var + 1e-5);
    g_bna[j] = a; g_bnd[j] = b[j] - (float)mu * a;
}

// ---------------- score + per-graph sums ----------------
__global__ void k_score(const int* __restrict__ row, const float* __restrict__ S) {
    __shared__ double sloc[2];
    __shared__ float Ss[CE], Ba[CE], Bd[CE];
    int t = threadIdx.x;
    if (t < 2) sloc[t] = 0.0;
    if (t < CE) { Ss[t] = S[t]; Ba[t] = g_bna[t]; Bd[t] = g_bnd[t]; }
    __syncthreads();
    int e = blockIdx.x * 256 + t;
    int g0 = row[min(blockIdx.x * 256, EE - 1)] / BLKG;
    if (e < EE) {
        int re = g_rev[e];
        float z = 0.f;
        #pragma unroll
        for (int k = 0; k < CE; k += 4) {
            float4 a = *(const float4*)&g_ea[e * CE + k];
            float4 b = *(const float4*)&g_ea[re * CE + k];
            z += (fmaxf(a.x * Ba[k]   + Bd[k],   0.f) + fmaxf(b.x * Ba[k]   + Bd[k],   0.f)) * Ss[k];
            z += (fmaxf(a.y * Ba[k+1] + Bd[k+1], 0.f) + fmaxf(b.y * Ba[k+1] + Bd[k+1], 0.f)) * Ss[k+1];
            z += (fmaxf(a.z * Ba[k+2] + Bd[k+2], 0.f) + fmaxf(b.z * Ba[k+2] + Bd[k+2], 0.f)) * Ss[k+2];
            z += (fmaxf(a.w * Ba[k+3] + Bd[k+3], 0.f) + fmaxf(b.w * Ba[k+3] + Bd[k+3], 0.f)) * Ss[k+3];
        }
        float s = 1.f / (1.f + expf(-z / g_snr));
        g_score[e] = s;
        int gg = row[e] / BLKG;
        atomicAdd(&sloc[gg == g0 ? 0 : 1], (double)s);
    }
    __syncthreads();
    if (t == 0) {
        atomicAdd(&g_gsum[g0], sloc[0]);
        int g1 = row[min(blockIdx.x * 256 + 255, EE - 1)] / BLKG;
        if (g1 != g0 && sloc[1] != 0.0) atomicAdd(&g_gsum[g1], sloc[1]);
    }
}

__global__ void k_gmean() {
    int g = threadIdx.x;
    if (g >= BBG) return;
    int c = g_rs[(g + 1) * BLKG] - g_rs[g * BLKG];
    g_gmean[g] = c ? (float)(g_gsum[g] / (double)c) : 0.f;
}

// ---------------- CC per graph, fused selection ----------------
__global__ void k_cc(const int* __restrict__ row, const int* __restrict__ col) {
    extern __shared__ u32 eb[];
    __shared__ int lab[BLKG];
    __shared__ int chg, rc, ecnt;
    int g = blockIdx.x, t = threadIdx.x;
    int base = g * BLKG;
    int e0 = g_rs[base], e1 = g_rs[base + BLKG];
    for (int i = t; i < BLKG; i += blockDim.x) lab[i] = i;
    if (t == 0) { chg = 1; rc = 0; ecnt = 0; }
    __syncthreads();
    float gm = g_gmean[g];
    for (int e = e0 + t; e < e1; e += blockDim.x) {
        float s = g_score[e];
        unsigned char sl = (s <= 0.5f) && (s < gm);
        g_sel[e] = sl;
        if (sl) {
            g_xmask[row[e]] = 1;
            int p = atomicAdd(&ecnt, 1);
            eb[p] = ((u32)(row[e] - base) << 10) | (u32)(col[e] - base);
        }
    }
    __syncthreads();
    int ne = ecnt;
    for (int it = 0; it < 256 && chg; it++) {
        __syncthreads();
        if (t == 0) chg = 0;
        __syncthreads();
        for (int i = t; i < ne; i += blockDim.x) {
            u32 p = eb[i];
            int r = p >> 10, c = p & 1023;
            int lr = lab[r], lc = lab[c];
            if (lr < lc) { if (atomicMin(&lab[c], lr) > lr) chg = 1; }
            else if (lc < lr) { if (atomicMin(&lab[r], lc) > lc) chg = 1; }
        }
        __syncthreads();
        for (int i = t; i < BLKG; i += blockDim.x) {
            int l = lab[i], ll = lab[l];
            if (ll < l) { lab[i] = ll; chg = 1; }
        }
        __syncthreads();
    }
    for (int i = t; i < BLKG; i += blockDim.x) {
        g_lab[base + i] = lab[i];
        if (lab[i] == i) atomicAdd(&rc, 1);
    }
    __syncthreads();
    if (t == 0) g_repcnt[g] = rc;
}

__global__ void k_scan64() {
    if (threadIdx.x == 0) {
        int a = 0;
        for (int g = 0; g < BBG; g++) { g_rb[g] = a; a += g_repcnt[g]; }
        g_rb[BBG] = a;
    }
}

__global__ void k_comp() {
    __shared__ int s[1024];
    int g = blockIdx.x, t = threadIdx.x;
    int base = g * BLKG;
    s[t] = (t < BLKG && g_lab[base + t] == t) ? 1 : 0;
    __syncthreads();
    for (int off = 1; off < 1024; off <<= 1) {
        int v = (t >= off) ? s[t - off] : 0;
        __syncthreads(); s[t] += v; __syncthreads();
    }
    if (t < BLKG) {
        int c = g_rb[g] + s[g_lab[base + t]] - 1;
        g_comp[base + t] = c;
        g_bout[c] = g;
    }
}

// ---------------- unique coalesce keys via smem hash ----------------
__global__ void k_unique(const int* __restrict__ row, const int* __restrict__ col) {
    extern __shared__ u32 sh[];
    u32* hkey  = sh;
    u32* hrank = sh + HSH;
    u32* ulist = sh + 2 * HSH;
    __shared__ int part[1024];
    int g = blockIdx.x, t = threadIdx.x;
    int e0 = g_rs[g * BLKG], e1 = g_rs[(g + 1) * BLKG];
    for (int i = t; i < HSH; i += 1024) hkey[i] = 0xFFFFFFFFu;
    __syncthreads();
    for (int e = e0 + t; e < e1; e += 1024) {
        if (g_sel[e]) continue;
        u32 key = (u32)g_comp[row[e]] * (u32)NN + (u32)g_comp[col[e]];
        u32 h = (key * 2654435761u) & (HSH - 1);
        while (true) {
            u32 old = atomicCAS(&hkey[h], 0xFFFFFFFFu, key);
            if (old == 0xFFFFFFFFu || old == key) break;
            h = (h + 1) & (HSH - 1);
        }
        g_erank[e] = (int)h;
    }
    __syncthreads();
    int i0 = t * 16, run = 0;
    for (int j = 0; j < 16; j++) run += (hkey[i0 + j] != 0xFFFFFFFFu);
    part[t] = run;
    __syncthreads();
    for (int off = 1; off < 1024; off <<= 1) {
        int v = (t >= off) ? part[t - off] : 0;
        __syncthreads(); part[t] += v; __syncthreads();
    }
    int base = t ? part[t - 1] : 0;
    int w = 0;
    for (int j = 0; j < 16; j++) {
        u32 k2 = hkey[i0 + j];
        if (k2 != 0xFFFFFFFFu) ulist[base + w++] = k2;
    }
    int U = part[1023];
    if (t == 0) g_ucnt[g] = U;
    __syncthreads();
    int P = 2; while (P < U) P <<= 1;
    for (int i = U + t; i < P; i += 1024) ulist[i] = 0xFFFFFFFFu;
    __syncthreads();
    for (u32 k = 2; k <= (u32)P; k <<= 1)
        for (u32 j = k >> 1; j; j >>= 1) {
            for (u32 i = t; i < (u32)P; i += 1024) {
                u32 ixj = i ^ j;
                if (ixj > i) {
                    u32 a = ulist[i], b = ulist[ixj];
                    bool up = ((i & k) == 0);
                    if ((a > b) == up) { ulist[i] = b; ulist[ixj] = a; }
                }
            }
            __syncthreads();
        }
    for (int p = t; p < U; p += 1024) {
        u32 key = ulist[p];
        u32 h = (key * 2654435761u) & (HSH - 1);
        while (hkey[h] != key) h = (h + 1) & (HSH - 1);
        hrank[h] = (u32)p;
        g_ukeys[g * SORTN + p] = key;
    }
    __syncthreads();
    for (int e = e0 + t; e < e1; e += 1024) {
        if (g_sel[e]) continue;
        g_erank[e] = (int)hrank[g_erank[e]];
    }
}

__global__ void k_uscan() {
    if (threadIdx.x == 0) {
        int a = 0;
        for (int g = 0; g < BBG; g++) { g_ub[g] = a; a += g_ucnt[g]; }
        g_ub[BBG] = a;
    }
}

// ---------------- EGIN message (bn/score fused) -> g_h ----------------
__global__ void k_msg2(const float* __restrict__ x, const float* __restrict__ Wedge,
                       const float* __restrict__ eps, const int* __restrict__ col) {
    __shared__ float Ws[CE * CX];
    __shared__ float Ba[CE], Bd[CE];
    int t = threadIdx.x;
    for (int i = t; i < CE * CX; i += 256) Ws[i] = Wedge[i];
    if (t < CE) { Ba[t] = g_bna[t]; Bd[t] = g_bnd[t]; }
    __syncthreads();
    int n = (blockIdx.x * 256 + t) >> 5;
    int l = t & 31;
    if (n >= NN) return;
    float4 agg = make_float4(0.f, 0.f, 0.f, 0.f);
    for (int e = g_rs[n]; e < g_rs[n + 1]; e++) {
        if (!g_sel[e]) continue;
        float sc = g_score[e];
        float4 m = make_float4(0.f, 0.f, 0.f, 0.f);
        #pragma unroll 8
        for (int k = 0; k < CE; k++) {
            float ek = fmaxf(__ldg(&g_ea[e * CE + k]) * Ba[k] + Bd[k], 0.f) * sc;
            float4 w = *(const float4*)&Ws[k * CX + l * 4];
            m.x += ek * w.x; m.y += ek * w.y; m.z += ek * w.z; m.w += ek * w.w;
        }
        const float4 xc = *(const float4*)&x[(size_t)col[e] * CX + l * 4];
        agg.x += fmaxf(m.x + xc.x, 0.f); agg.y += fmaxf(m.y + xc.y, 0.f);
        agg.z += fmaxf(m.z + xc.z, 0.f); agg.w += fmaxf(m.w + xc.w, 0.f);
    }
    float ep = 1.f + eps[0];
    const float4 xn = *(const float4*)&x[(size_t)n * CX + l * 4];
    float4 h = make_float4(ep * xn.x + agg.x, ep * xn.y + agg.y,
                           ep * xn.z + agg.z, ep * xn.w + agg.w);
    *(float4*)&g_h[(size_t)n * CX + l * 4] = h;
}

// ---------------- fused TF32 double GEMM: xc = (relu(h@W1+b1))@W2 + b2 ---------
__global__ void k_gemmF(const float* __restrict__ W1, const float* __restrict__ b1,
                        const float* __restrict__ W2, const float* __restrict__ b2) {
    extern __shared__ float sm[];
    float* Ct = sm;            // 128x128 = 16384 floats
    float* Ap = sm + 16384;    // 128x8
    float* Bp = sm + 17408;    // 8x128
    int t = threadIdx.x;
    int m0 = blockIdx.x * 128;
    int warp = t >> 5;
    int wm = (warp & 3) << 5;   // 0/32/64/96
    int wn = (warp >> 2) << 6;  // 0/64
    wmma::fragment<wmma::accumulator, 16, 16, 8, float> acc[2][4];
    #pragma unroll
    for (int i = 0; i < 2; i++)
        #pragma unroll
        for (int j = 0; j < 4; j++) wmma::fill_fragment(acc[i][j], 0.f);
    int ar = t >> 1, ac = (t & 1) << 2;
    int bi = t << 2, br = bi >> 7, bc = bi & 127;
    // ---- GEMM1: h @ W1 ----
    for (int k0 = 0; k0 < CX; k0 += 8) {
        float4 av = *(const float4*)&g_h[(size_t)(m0 + ar) * CX + k0 + ac];
        Ap[ar * 8 + ac]     = wmma::__float_to_tf32(av.x);
        Ap[ar * 8 + ac + 1] = wmma::__float_to_tf32(av.y);
        Ap[ar * 8 + ac + 2] = wmma::__float_to_tf32(av.z);
        Ap[ar * 8 + ac + 3] = wmma::__float_to_tf32(av.w);
        float4 bv = *(const float4*)&W1[(size_t)(k0 + br) * CX + bc];
        Bp[br * 128 + bc]     = wmma::__float_to_tf32(bv.x);
        Bp[br * 128 + bc + 1] = wmma::__float_to_tf32(bv.y);
        Bp[br * 128 + bc + 2] = wmma::__float_to_tf32(bv.z);
        Bp[br * 128 + bc + 3] = wmma::__float_to_tf32(bv.w);
        __syncthreads();
        wmma::fragment<wmma::matrix_a, 16, 16, 8, wmma::precision::tf32, wmma::row_major> fa;
        wmma::fragment<wmma::matrix_b, 16, 16, 8, wmma::precision::tf32, wmma::row_major> fb[4];
        #pragma unroll
        for (int j = 0; j < 4; j++) wmma::load_matrix_sync(fb[j], Bp + wn + j * 16, 128);
        #pragma unroll
        for (int i = 0; i < 2; i++) {
            wmma::load_matrix_sync(fa, Ap + (wm + i * 16) * 8, 8);
            #pragma unroll
            for (int j = 0; j < 4; j++) wmma::mma_sync(acc[i][j], fa, fb[j], acc[i][j]);
        }
        __syncthreads();
    }
    #pragma unroll
    for (int i = 0; i < 2; i++)
        #pragma unroll
        for (int j = 0; j < 4; j++)
            wmma::store_matrix_sync(Ct + (wm + i * 16) * 128 + wn + j * 16, acc[i][j],
                                    128, wmma::mem_row_major);
    __syncthreads();
    // bias + relu + tf32 convert in place
    for (int idx = t * 4; idx < 16384; idx += 1024) {
        int colb = idx & 127;
        float4 v = *(float4*)&Ct[idx];
        float4 bb = *(const float4*)&b1[colb];
        v.x = wmma::__float_to_tf32(fmaxf(v.x + bb.x, 0.f));
        v.y = wmma::__float_to_tf32(fmaxf(v.y + bb.y, 0.f));
        v.z = wmma::__float_to_tf32(fmaxf(v.z + bb.z, 0.f));
        v.w = wmma::__float_to_tf32(fmaxf(v.w + bb.w, 0.f));
        *(float4*)&Ct[idx] = v;
    }
    __syncthreads();
    // ---- GEMM2: t1 (in Ct) @ W2 ----
    #pragma unroll
    for (int i = 0; i < 2; i++)
        #pragma unroll
        for (int j = 0; j < 4; j++) wmma::fill_fragment(acc[i][j], 0.f);
    for (int k0 = 0; k0 < CX; k0 += 8) {
        float4 bv = *(const float4*)&W2[(size_t)(k0 + br) * CX + bc];
        Bp[br * 128 + bc]     = wmma::__float_to_tf32(bv.x);
        Bp[br * 128 + bc + 1] = wmma::__float_to_tf32(bv.y);
        Bp[br * 128 + bc + 2] = wmma::__float_to_tf32(bv.z);
        Bp[br * 128 + bc + 3] = wmma::__float_to_tf32(bv.w);
        __syncthreads();
        wmma::fragment<wmma::matrix_a, 16, 16, 8, wmma::precision::tf32, wmma::row_major> fa;
        wmma::fragment<wmma::matrix_b, 16, 16, 8, wmma::precision::tf32, wmma::row_major> fb[4];
        #pragma unroll
        for (int j = 0; j < 4; j++) wmma::load_matrix_sync(fb[j], Bp + wn + j * 16, 128);
        #pragma unroll
        for (int i = 0; i < 2; i++) {
            wmma::load_matrix_sync(fa, Ct + (wm + i * 16) * 128 + k0, 128);
            #pragma unroll
            for (int j = 0; j < 4; j++) wmma::mma_sync(acc[i][j], fa, fb[j], acc[i][j]);
        }
        __syncthreads();
    }
    #pragma unroll
    for (int i = 0; i < 2; i++)
        #pragma unroll
        for (int j = 0; j < 4; j++)
            wmma::store_matrix_sync(Ct + (wm + i * 16) * 128 + wn + j * 16, acc[i][j],
                                    128, wmma::mem_row_major);
    __syncthreads();
    for (int idx = t * 4; idx < 16384; idx += 1024) {
        int colb = idx & 127;
        int m = m0 + (idx >> 7);
        float4 v = *(float4*)&Ct[idx];
        float4 bb = *(const float4*)&b2[colb];
        *(float4*)&g_xc[(size_t)m * CX + colb] =
            make_float4(v.x + bb.x, v.y + bb.y, v.z + bb.z, v.w + bb.w);
    }
}

// ---------------- pooling ----------------
__global__ void k_pool(const float* __restrict__ x) {
    int i = blockIdx.x * blockDim.x + threadIdx.x;
    if (i >= NN * 32) return;
    int n = i >> 5, q = (i & 31) * 4;
    int c = g_comp[n];
    if (g_xmask[n]) {
        float4 v = *(const float4*)&g_xc[(size_t)n * CX + q];
        atomicAdd(&g_pa[(size_t)c * CX + q], v.x); atomicAdd(&g_pa[(size_t)c * CX + q + 1], v.y);
        atomicAdd(&g_pa[(size_t)c * CX + q + 2], v.z); atomicAdd(&g_pa[(size_t)c * CX + q + 3], v.w);
    } else {
        float4 v = *(const float4*)&x[(size_t)n * CX + q];
        atomicAdd(&g_pb[(size_t)c * CX + q], v.x); atomicAdd(&g_pb[(size_t)c * CX + q + 1], v.y);
        atomicAdd(&g_pb[(size_t)c * CX + q + 2], v.z); atomicAdd(&g_pb[(size_t)c * CX + q + 3], v.w);
        if ((i & 31) == 0) g_has[c] = 1;
    }
}

__global__ void k_xout(float* out) {
    int i = blockIdx.x * blockDim.x + threadIdx.x;
    if (i >= NN * 32) return;
    int cl = i >> 5, q = (i & 31) * 4;
    int h = g_has[cl];
    float4 a = *(float4*)&g_pa[(size_t)cl * CX + q];
    float4 b = *(float4*)&g_pb[(size_t)cl * CX + q];
    float4 o = h ? b : a;
    *(float4*)&out[OFF_X + (size_t)cl * CX + q] = o;
    if ((i & 31) == 0) out[OFF_BATCH + cl] = (float)g_bout[cl];
    if (cl < g_rb[BBG]) {
        int bg = g_bout[cl];
        atomicAdd(&g_xg[bg * CX + q], o.x); atomicAdd(&g_xg[bg * CX + q + 1], o.y);
        atomicAdd(&g_xg[bg * CX + q + 2], o.z); atomicAdd(&g_xg[bg * CX + q + 3], o.w);
    }
}

__global__ void k_bnxg(const float* __restrict__ g, const float* __restrict__ b, float* out) {
    int c = threadIdx.x;
    if (c >= CX) return;
    double s = 0.0, q = 0.0;
    for (int i = 0; i < BBG; i++) { double v = g_xg[i * CX + c]; s += v; q += v * v; }
    double mu = s / BBG, var = q / BBG - mu * mu;
    float a = g[c] / (float)sqrt(var + 1e-5);
    float d = b[c] - (float)mu * a;
    for (int i = 0; i < BBG; i++) out[OFF_XG + i * CX + c] = g_xg[i * CX + c] * a + d;
}

// ---------------- emit edge_index_out ----------------
__global__ void k_eio(float* out) {
    int g = blockIdx.x, t = threadIdx.x;
    int U = g_ucnt[g], ub = g_ub[g];
    for (int p = t; p < U; p += 256) {
        u32 key = g_ukeys[g * SORTN + p];
        int seg = ub + p;
        out[OFF_EIO + seg] = (float)(key / (u32)NN);
        out[OFF_EIO + EE + seg] = (float)(key % (u32)NN);
    }
}

// ---------------- emit attr: lane=channel, warp walks 8 edges, run-reduce ------
__global__ void k_emit2(const int* __restrict__ row, float* out) {
    __shared__ float Ba[CE], Bd[CE];
    int t = threadIdx.x;
    if (t < CE) { Ba[t] = g_bna[t]; Bd[t] = g_bnd[t]; }
    __syncthreads();
    int wid = (blockIdx.x * 256 + t) >> 5;
    int l = t & 31;
    int e0 = wid * 8;
    float acc = 0.f;
    int cur = -1;
    for (int j = 0; j < 8; j++) {
        int e = e0 + j;
        if (e >= EE) break;
        if (g_sel[e]) continue;
        int g = row[e] / BLKG;
        int seg = g_ub[g] + g_erank[e];
        float v = fmaxf(g_ea[e * CE + l] * Ba[l] + Bd[l], 0.f) * g_score[e];
        if (seg != cur) {
            if (cur >= 0) atomicAdd(&out[OFF_ATTR + (size_t)cur * CE + l], acc);
            cur = seg; acc = 0.f;
        }
        acc += v;
    }
    if (cur >= 0) atomicAdd(&out[OFF_ATTR + (size_t)cur * CE + l], acc);
}

extern "C" void kernel_launch(void* const* d_in, const int* in_sizes, int n_in,
                              void* d_out, int out_size) {
    const float* x = (const float*)d_in[0];
    const int* ei = (const int*)d_in[1];
    const float* eattr = (const float*)d_in[2];
    const float* S = (const float*)d_in[4];
    const float* We = (const float*)d_in[5];
    const float* be = (const float*)d_in[6];
    const float* bn_e_g = (const float*)d_in[7];
    const float* bn_e_b = (const float*)d_in[8];
    const float* Wedge = (const float*)d_in[9];
    const float* eps = (const float*)d_in[10];
    const float* W1 = (const float*)d_in[11];
    const float* b1 = (const float*)d_in[12];
    const float* W2 = (const float*)d_in[13];
    const float* b2 = (const float*)d_in[14];
    const float* bn_g = (const float*)d_in[15];
    const float* bn_b = (const float*)d_in[16];
    float* out = (float*)d_out;
    const int* row = ei;
    const int* col = ei + EE;

    cudaFuncSetAttribute(k_unique, cudaFuncAttributeMaxDynamicSharedMemorySize, 3 * HSH * 4);
    cudaFuncSetAttribute(k_cc, cudaFuncAttributeMaxDynamicSharedMemorySize, HSH * 4);
    cudaFuncSetAttribute(k_gemmF, cudaFuncAttributeMaxDynamicSharedMemorySize, 18432 * 4);

    void *pa, *pb, *xg, *bnstat, *gsum, *xmask, *has, *bout;
    cudaGetSymbolAddress(&pa, g_pa);
    cudaGetSymbolAddress(&pb, g_pb);
    cudaGetSymbolAddress(&xg, g_xg);
    cudaGetSymbolAddress(&bnstat, g_bnstat);
    cudaGetSymbolAddress(&gsum, g_gsum);
    cudaGetSymbolAddress(&xmask, g_xmask);
    cudaGetSymbolAddress(&has, g_has);
    cudaGetSymbolAddress(&bout, g_bout);
    cudaMemsetAsync(out + OFF_ATTR, 0, (size_t)EE * CE * 4);
    cudaMemsetAsync(pa, 0, (size_t)NN * CX * 4);
    cudaMemsetAsync(pb, 0, (size_t)NN * CX * 4);
    cudaMemsetAsync(xg, 0, (size_t)BBG * CX * 4);
    cudaMemsetAsync(bnstat, 0, 2 * CE * 8);
    cudaMemsetAsync(gsum, 0, BBG * 8);
    cudaMemsetAsync(xmask, 0, NN * 4);
    cudaMemsetAsync(has, 0, NN * 4);
    cudaMemsetAsync(bout, 0, NN * 4);

    k_fill<<<(2 * EE + 255) / 256, 256>>>(out);
    k_rowstart<<<(NN + 256) / 256, 256>>>(row);
    k_rev<<<(EE + 255) / 256, 256>>>(row, col);
    k_nodesum<<<(NN * 32 + 255) / 256, 256>>>(eattr);
    k_lin<<<(EE + 255) / 256, 256>>>(row, eattr, We, be);
    k_bnfin<<<1, 32>>>(bn_e_g, bn_e_b, S);
    k_score<<<(EE + 255) / 256, 256>>>(row, S);
    k_gmean<<<1, 64>>>();
    k_cc<<<BBG, 768, HSH * 4>>>(row, col);
    k_scan64<<<1, 32>>>();
    k_comp<<<BBG, 1024>>>();
    k_unique<<<BBG, 1024, 3 * HSH * 4>>>(row, col);
    k_uscan<<<1, 32>>>();
    k_msg2<<<(NN * 32 + 255) / 256, 256>>>(x, Wedge, eps, col);
    k_gemmF<<<NN / 128, 256, 18432 * 4>>>(W1, b1, W2, b2);
    k_pool<<<(NN * 32 + 255) / 256, 256>>>(x);
    k_xout<<<(NN * 32 + 255) / 256, 256>>>(out);
    k_bnxg<<<1, 128>>>(bn_g, bn_b, out);
    k_eio<<<BBG, 256>>>(out);
    k_emit2<<<(EE / 8 * 32 + 255) / 256, 256>>>(row, out);
}